// round 13
// baseline (speedup 1.0000x reference)
#include <cuda_runtime.h>
#include <cuda_bf16.h>
#include <cuda_fp16.h>
#include <cstdint>

#define HID 1024
#define NEG_SLOPE 0.2f

static const int NMAX = 10240;
static const int EMAX = 163840;
#define TMAX (EMAX + NMAX)

// ---------------- scratch (static device globals) ----------------
__device__ __align__(16) float g_xl[(size_t)NMAX * HID];
__device__ __align__(16) float g_xr[(size_t)NMAX * HID];
__device__ __align__(16) __half g_xlh[(size_t)NMAX * HID];   // fp16 copy for aggregation
__device__ __align__(16) float g_e [TMAX];
__device__ int   g_deg[NMAX];
__device__ int   g_cur[NMAX];
__device__ int   g_off[NMAX + 1];
__device__ int   g_srcs[TMAX];
__device__ int   g_dsts[TMAX];

// fp16 activations (2-term GEMM path)
__device__ __align__(16) __half g_xh[(size_t)NMAX * 512];
__device__ __align__(16) __half g_hh[(size_t)NMAX * HID];
// bf16 hi/lo activations (3-term path for W2/Wc)
__device__ __align__(16) __nv_bfloat16 g_h1h[(size_t)NMAX * 512];
__device__ __align__(16) __nv_bfloat16 g_h1l[(size_t)NMAX * 512];
__device__ __align__(16) __nv_bfloat16 g_h2h[(size_t)NMAX * 128];
__device__ __align__(16) __nv_bfloat16 g_h2l[(size_t)NMAX * 128];

// transposed + split weights: Wt[n][k]
__device__ __align__(16) __half g_Wlrt_h[2048 * 512], g_Wlrt_l[2048 * 512];
__device__ __align__(16) __half g_W1t_h[512 * 1024],  g_W1t_l[512 * 1024];
__device__ __align__(16) __nv_bfloat16 g_W2t_h[128 * 512], g_W2t_l[128 * 512];
__device__ __align__(16) __nv_bfloat16 g_Wct_h[112 * 128], g_Wct_l[112 * 128];

// ---------------- PTX helpers ----------------
__device__ __forceinline__ uint32_t smem_u32(const void* p) {
    uint32_t a;
    asm("{ .reg .u64 t; cvta.to.shared.u64 t, %1; cvt.u32.u64 %0, t; }"
        : "=r"(a) : "l"(p));
    return a;
}
__device__ __forceinline__ void cp16(uint32_t saddr, const void* gaddr, int srcsize) {
    asm volatile("cp.async.cg.shared.global [%0], [%1], 16, %2;"
                 :: "r"(saddr), "l"(gaddr), "r"(srcsize) : "memory");
}
#define CP_COMMIT() asm volatile("cp.async.commit_group;" ::: "memory")
#define CP_WAIT(n)  asm volatile("cp.async.wait_group %0;" :: "n"(n) : "memory")

__device__ __forceinline__ void ldsm4(uint32_t& r0, uint32_t& r1, uint32_t& r2,
                                      uint32_t& r3, uint32_t a) {
    asm volatile("ldmatrix.sync.aligned.m8n8.x4.shared.b16 {%0,%1,%2,%3}, [%4];"
                 : "=r"(r0), "=r"(r1), "=r"(r2), "=r"(r3) : "r"(a));
}
__device__ __forceinline__ void mma_bf16(float* d, const uint32_t* a,
                                         uint32_t b0, uint32_t b1) {
    asm volatile(
        "mma.sync.aligned.m16n8k16.row.col.f32.bf16.bf16.f32 "
        "{%0,%1,%2,%3}, {%4,%5,%6,%7}, {%8,%9}, {%0,%1,%2,%3};"
        : "+f"(d[0]), "+f"(d[1]), "+f"(d[2]), "+f"(d[3])
        : "r"(a[0]), "r"(a[1]), "r"(a[2]), "r"(a[3]), "r"(b0), "r"(b1));
}
__device__ __forceinline__ void mma_f16(float* d, const uint32_t* a,
                                        uint32_t b0, uint32_t b1) {
    asm volatile(
        "mma.sync.aligned.m16n8k16.row.col.f32.f16.f16.f32 "
        "{%0,%1,%2,%3}, {%4,%5,%6,%7}, {%8,%9}, {%0,%1,%2,%3};"
        : "+f"(d[0]), "+f"(d[1]), "+f"(d[2]), "+f"(d[3])
        : "r"(a[0]), "r"(a[1]), "r"(a[2]), "r"(a[3]), "r"(b0), "r"(b1));
}

#define TILE_B   8192

__device__ __forceinline__ void fill_tile_async(
    uint32_t dst, const void* __restrict__ src2B,
    int rowbase, int limit, int K, int k0, int tid)
{
    int fr = tid >> 2;
    int fc = tid & 3;
#pragma unroll
    for (int it = 0; it < 2; it++) {
        int row = fr + it * 64;
        int grow = rowbase + row;
        uint32_t saddr = dst + row * 64 + ((fc ^ ((row >> 1) & 3)) * 16);
        const char* g = (const char*)src2B + ((size_t)grow * K + k0 + fc * 8) * 2;
        cp16(saddr, g, (grow < limit) ? 16 : 0);
    }
}

// ============================================================================
// bf16 3-term GEMM (used for W2, Wc)
// ============================================================================
#define STAGE_B  (4 * TILE_B)
#define GSMEM    (2 * STAGE_B)

template <bool RELU, bool WF32, bool WBF16>
__global__ __launch_bounds__(256, 1)
void gemm_mma(const __nv_bfloat16* __restrict__ Ah, const __nv_bfloat16* __restrict__ Al,
              const __nv_bfloat16* __restrict__ Bh, const __nv_bfloat16* __restrict__ Bl,
              const float* __restrict__ bias,
              float* __restrict__ C,
              __nv_bfloat16* __restrict__ Ch, __nv_bfloat16* __restrict__ Cl,
              int M, int Nn, int K)
{
    extern __shared__ char smem[];
    const uint32_t sb = smem_u32(smem);
    const int tid = threadIdx.x;
    const int wid = tid >> 5;
    const int lane = tid & 31;
    const int row0 = blockIdx.y * 128;
    const int col0 = blockIdx.x * 128;
    const int wm0 = (wid & 3) * 32;
    const int wn0 = (wid >> 2) * 64;

    float acc[2][8][4];
#pragma unroll
    for (int i = 0; i < 2; i++)
#pragma unroll
        for (int j = 0; j < 8; j++)
#pragma unroll
            for (int k = 0; k < 4; k++) acc[i][j][k] = 0.f;

    uint32_t aoff[2][2], boff[4][2];
#pragma unroll
    for (int mt = 0; mt < 2; mt++) {
        int arow = wm0 + mt * 16 + (lane & 15);
        int hi = lane >> 4;
#pragma unroll
        for (int s = 0; s < 2; s++) {
            int chunk = s * 2 + hi;
            aoff[mt][s] = arow * 64 + ((chunk ^ ((arow >> 1) & 3)) * 16);
        }
    }
#pragma unroll
    for (int bt = 0; bt < 4; bt++) {
        int brow = wn0 + bt * 16 + (lane & 7) + ((lane >> 4) & 1) * 8;
        int hi = (lane >> 3) & 1;
#pragma unroll
        for (int s = 0; s < 2; s++) {
            int chunk = s * 2 + hi;
            boff[bt][s] = brow * 64 + ((chunk ^ ((brow >> 1) & 3)) * 16);
        }
    }

    const int nC = K / 32;
    {
        uint32_t st = sb;
        fill_tile_async(st + 0 * TILE_B, Ah, row0, M,  K, 0, tid);
        fill_tile_async(st + 1 * TILE_B, Al, row0, M,  K, 0, tid);
        fill_tile_async(st + 2 * TILE_B, Bh, col0, Nn, K, 0, tid);
        fill_tile_async(st + 3 * TILE_B, Bl, col0, Nn, K, 0, tid);
        CP_COMMIT();
    }

    for (int c = 0; c < nC; c++) {
        const uint32_t st = sb + (c & 1) * STAGE_B;
        if (c + 1 < nC) {
            uint32_t nx = sb + ((c + 1) & 1) * STAGE_B;
            int k0 = (c + 1) * 32;
            fill_tile_async(nx + 0 * TILE_B, Ah, row0, M,  K, k0, tid);
            fill_tile_async(nx + 1 * TILE_B, Al, row0, M,  K, k0, tid);
            fill_tile_async(nx + 2 * TILE_B, Bh, col0, Nn, K, k0, tid);
            fill_tile_async(nx + 3 * TILE_B, Bl, col0, Nn, K, k0, tid);
            CP_COMMIT();
            CP_WAIT(1);
        } else {
            CP_WAIT(0);
        }
        __syncthreads();

#pragma unroll
        for (int s = 0; s < 2; s++) {
            uint32_t ah[2][4], al[2][4], bh[4][4], bl[4][4];
#pragma unroll
            for (int mt = 0; mt < 2; mt++) {
                ldsm4(ah[mt][0], ah[mt][1], ah[mt][2], ah[mt][3],
                      st + 0 * TILE_B + aoff[mt][s]);
                ldsm4(al[mt][0], al[mt][1], al[mt][2], al[mt][3],
                      st + 1 * TILE_B + aoff[mt][s]);
            }
#pragma unroll
            for (int bt = 0; bt < 4; bt++) {
                ldsm4(bh[bt][0], bh[bt][1], bh[bt][2], bh[bt][3],
                      st + 2 * TILE_B + boff[bt][s]);
                ldsm4(bl[bt][0], bl[bt][1], bl[bt][2], bl[bt][3],
                      st + 3 * TILE_B + boff[bt][s]);
            }
#pragma unroll
            for (int mt = 0; mt < 2; mt++) {
#pragma unroll
                for (int bt = 0; bt < 4; bt++) {
                    mma_bf16(acc[mt][2 * bt + 0], ah[mt], bh[bt][0], bh[bt][1]);
                    mma_bf16(acc[mt][2 * bt + 1], ah[mt], bh[bt][2], bh[bt][3]);
                    mma_bf16(acc[mt][2 * bt + 0], ah[mt], bl[bt][0], bl[bt][1]);
                    mma_bf16(acc[mt][2 * bt + 1], ah[mt], bl[bt][2], bl[bt][3]);
                    mma_bf16(acc[mt][2 * bt + 0], al[mt], bh[bt][0], bh[bt][1]);
                    mma_bf16(acc[mt][2 * bt + 1], al[mt], bh[bt][2], bh[bt][3]);
                }
            }
        }
        __syncthreads();
    }

#pragma unroll
    for (int mt = 0; mt < 2; mt++) {
#pragma unroll
        for (int nt = 0; nt < 8; nt++) {
            int col = col0 + wn0 + nt * 8 + (lane & 3) * 2;
            if (col >= Nn) continue;
            float bx = bias[col], by = bias[col + 1];
#pragma unroll
            for (int half = 0; half < 2; half++) {
                int grow = row0 + wm0 + mt * 16 + (lane >> 2) + half * 8;
                if (grow >= M) continue;
                float ox = acc[mt][nt][half * 2 + 0] + bx;
                float oy = acc[mt][nt][half * 2 + 1] + by;
                if (RELU) { ox = fmaxf(ox, 0.f); oy = fmaxf(oy, 0.f); }
                size_t idx = (size_t)grow * Nn + col;
                if (WF32) {
                    *(float2*)(C + idx) = make_float2(ox, oy);
                }
                if (WBF16) {
                    __nv_bfloat16 hx = __float2bfloat16(ox);
                    __nv_bfloat16 hy = __float2bfloat16(oy);
                    *(__nv_bfloat162*)(Ch + idx) = __nv_bfloat162(hx, hy);
                    *(__nv_bfloat162*)(Cl + idx) = __floats2bfloat162_rn(
                        ox - __bfloat162float(hx), oy - __bfloat162float(hy));
                }
            }
        }
    }
}

// ============================================================================
// fp16 2-term GEMM (A single fp16, B hi/lo).  SPLITC: cols<1024 -> xl (fp32 +
// fp16 copy), cols>=1024 -> xr (fp32).
// ============================================================================
#define STAGE_H  (3 * TILE_B)
#define GSMEM_H  (2 * STAGE_H)

template <bool RELU, bool WF32, bool WBF16, bool SPLITC>
__global__ __launch_bounds__(256, 1)
void gemm_mma_h(const __half* __restrict__ Ah,
                const __half* __restrict__ Bh, const __half* __restrict__ Bl,
                const float* __restrict__ bias, const float* __restrict__ bias2,
                float* __restrict__ C, float* __restrict__ C2,
                __half* __restrict__ Cxh,
                __nv_bfloat16* __restrict__ Chb, __nv_bfloat16* __restrict__ Clb,
                int M, int Nn, int K)
{
    extern __shared__ char smem[];
    const uint32_t sb = smem_u32(smem);
    const int tid = threadIdx.x;
    const int wid = tid >> 5;
    const int lane = tid & 31;
    const int row0 = blockIdx.y * 128;
    const int col0 = blockIdx.x * 128;
    const int wm0 = (wid & 3) * 32;
    const int wn0 = (wid >> 2) * 64;

    float acc[2][8][4];
#pragma unroll
    for (int i = 0; i < 2; i++)
#pragma unroll
        for (int j = 0; j < 8; j++)
#pragma unroll
            for (int k = 0; k < 4; k++) acc[i][j][k] = 0.f;

    uint32_t aoff[2][2], boff[4][2];
#pragma unroll
    for (int mt = 0; mt < 2; mt++) {
        int arow = wm0 + mt * 16 + (lane & 15);
        int hi = lane >> 4;
#pragma unroll
        for (int s = 0; s < 2; s++) {
            int chunk = s * 2 + hi;
            aoff[mt][s] = arow * 64 + ((chunk ^ ((arow >> 1) & 3)) * 16);
        }
    }
#pragma unroll
    for (int bt = 0; bt < 4; bt++) {
        int brow = wn0 + bt * 16 + (lane & 7) + ((lane >> 4) & 1) * 8;
        int hi = (lane >> 3) & 1;
#pragma unroll
        for (int s = 0; s < 2; s++) {
            int chunk = s * 2 + hi;
            boff[bt][s] = brow * 64 + ((chunk ^ ((brow >> 1) & 3)) * 16);
        }
    }

    const int nC = K / 32;
    {
        uint32_t st = sb;
        fill_tile_async(st + 0 * TILE_B, Ah, row0, M,  K, 0, tid);
        fill_tile_async(st + 1 * TILE_B, Bh, col0, Nn, K, 0, tid);
        fill_tile_async(st + 2 * TILE_B, Bl, col0, Nn, K, 0, tid);
        CP_COMMIT();
    }

    for (int c = 0; c < nC; c++) {
        const uint32_t st = sb + (c & 1) * STAGE_H;
        if (c + 1 < nC) {
            uint32_t nx = sb + ((c + 1) & 1) * STAGE_H;
            int k0 = (c + 1) * 32;
            fill_tile_async(nx + 0 * TILE_B, Ah, row0, M,  K, k0, tid);
            fill_tile_async(nx + 1 * TILE_B, Bh, col0, Nn, K, k0, tid);
            fill_tile_async(nx + 2 * TILE_B, Bl, col0, Nn, K, k0, tid);
            CP_COMMIT();
            CP_WAIT(1);
        } else {
            CP_WAIT(0);
        }
        __syncthreads();

#pragma unroll
        for (int s = 0; s < 2; s++) {
            uint32_t ah[2][4], bh[4][4], bl[4][4];
#pragma unroll
            for (int mt = 0; mt < 2; mt++) {
                ldsm4(ah[mt][0], ah[mt][1], ah[mt][2], ah[mt][3],
                      st + 0 * TILE_B + aoff[mt][s]);
            }
#pragma unroll
            for (int bt = 0; bt < 4; bt++) {
                ldsm4(bh[bt][0], bh[bt][1], bh[bt][2], bh[bt][3],
                      st + 1 * TILE_B + boff[bt][s]);
                ldsm4(bl[bt][0], bl[bt][1], bl[bt][2], bl[bt][3],
                      st + 2 * TILE_B + boff[bt][s]);
            }
#pragma unroll
            for (int mt = 0; mt < 2; mt++) {
#pragma unroll
                for (int bt = 0; bt < 4; bt++) {
                    mma_f16(acc[mt][2 * bt + 0], ah[mt], bh[bt][0], bh[bt][1]);
                    mma_f16(acc[mt][2 * bt + 1], ah[mt], bh[bt][2], bh[bt][3]);
                    mma_f16(acc[mt][2 * bt + 0], ah[mt], bl[bt][0], bl[bt][1]);
                    mma_f16(acc[mt][2 * bt + 1], ah[mt], bl[bt][2], bl[bt][3]);
                }
            }
        }
        __syncthreads();
    }

#pragma unroll
    for (int mt = 0; mt < 2; mt++) {
#pragma unroll
        for (int nt = 0; nt < 8; nt++) {
            int col = col0 + wn0 + nt * 8 + (lane & 3) * 2;
            if (col >= Nn) continue;
            const float* bp = bias;
            float* Cp = C;
            int ccol = col;
            int cw = Nn;
            bool isXl = true;
            if (SPLITC) {
                cw = 1024;
                if (col >= 1024) { bp = bias2; Cp = C2; ccol = col - 1024; isXl = false; }
            }
            float bx = bp[ccol], by = bp[ccol + 1];
#pragma unroll
            for (int half = 0; half < 2; half++) {
                int grow = row0 + wm0 + mt * 16 + (lane >> 2) + half * 8;
                if (grow >= M) continue;
                float ox = acc[mt][nt][half * 2 + 0] + bx;
                float oy = acc[mt][nt][half * 2 + 1] + by;
                if (RELU) { ox = fmaxf(ox, 0.f); oy = fmaxf(oy, 0.f); }
                if (WF32) {
                    *(float2*)(Cp + (size_t)grow * cw + ccol) = make_float2(ox, oy);
                    if (SPLITC && isXl) {
                        *(__half2*)(Cxh + (size_t)grow * 1024 + ccol) =
                            __floats2half2_rn(ox, oy);
                    }
                }
                if (WBF16) {
                    size_t idx = (size_t)grow * Nn + col;
                    __nv_bfloat16 hx = __float2bfloat16(ox);
                    __nv_bfloat16 hy = __float2bfloat16(oy);
                    *(__nv_bfloat162*)(Chb + idx) = __nv_bfloat162(hx, hy);
                    *(__nv_bfloat162*)(Clb + idx) = __floats2bfloat162_rn(
                        ox - __bfloat162float(hx), oy - __bfloat162float(hy));
                }
            }
        }
    }
}

// ============================================================================
// Conversions / prep (single launch: split_x + all weight splits + count + init)
// ============================================================================
__device__ __forceinline__ void tsplit_block_bf(
    const float* __restrict__ W, __nv_bfloat16* __restrict__ th,
    __nv_bfloat16* __restrict__ tl, int K, int N, int bx, int by, int tid)
{
    __shared__ float t[32][33];
    int k0 = by * 32, n0 = bx * 32;
    int tx = tid & 31, ty = tid >> 5;
#pragma unroll
    for (int i = 0; i < 4; i++) {
        int k = k0 + ty + i * 8;
        t[ty + i * 8][tx] = (k < K && n0 + tx < N) ? W[(size_t)k * N + n0 + tx] : 0.f;
    }
    __syncthreads();
#pragma unroll
    for (int i = 0; i < 4; i++) {
        int n = n0 + ty + i * 8;
        int k = k0 + tx;
        if (n < N && k < K) {
            float v = t[tx][ty + i * 8];
            __nv_bfloat16 hb = __float2bfloat16(v);
            th[(size_t)n * K + k] = hb;
            tl[(size_t)n * K + k] = __float2bfloat16(v - __bfloat162float(hb));
        }
    }
}
__device__ __forceinline__ void tsplit_block_h(
    const float* __restrict__ W, __half* __restrict__ th,
    __half* __restrict__ tl, int K, int N, int bx, int by, int tid)
{
    __shared__ float t[32][33];
    int k0 = by * 32, n0 = bx * 32;
    int tx = tid & 31, ty = tid >> 5;
#pragma unroll
    for (int i = 0; i < 4; i++) {
        int k = k0 + ty + i * 8;
        t[ty + i * 8][tx] = (k < K && n0 + tx < N) ? W[(size_t)k * N + n0 + tx] : 0.f;
    }
    __syncthreads();
#pragma unroll
    for (int i = 0; i < 4; i++) {
        int n = n0 + ty + i * 8;
        int k = k0 + tx;
        if (n < N && k < K) {
            float v = t[tx][ty + i * 8];
            __half hb = __float2half_rn(v);
            th[(size_t)n * K + k] = hb;
            tl[(size_t)n * K + k] = __float2half_rn(v - __half2float(hb));
        }
    }
}

__global__ __launch_bounds__(256)
void prep_kernel(const float* __restrict__ x, const int* __restrict__ dstA,
                 const float* __restrict__ Wl, const float* __restrict__ Wr,
                 const float* __restrict__ W1, const float* __restrict__ W2,
                 const float* __restrict__ Wc,
                 __half* Wlrt_h, __half* Wlrt_l,
                 __half* W1t_h, __half* W1t_l,
                 __nv_bfloat16* W2t_h, __nv_bfloat16* W2t_l,
                 __nv_bfloat16* Wct_h, __nv_bfloat16* Wct_l,
                 __half* xh,
                 int n, int E, int nSplit, int nCount)
{
    int b = blockIdx.x;
    int tid = threadIdx.x;
    if (b < nSplit) {                                 // x -> fp16
        int i = b * 256 + tid;                        // float4 index
        int n4 = n * 128;
        if (i < n4) {
            float4 v = ((const float4*)x)[i];
            __half2* h2 = (__half2*)xh;
            h2[i * 2 + 0] = __floats2half2_rn(v.x, v.y);
            h2[i * 2 + 1] = __floats2half2_rn(v.z, v.w);
        }
    } else if (b < nSplit + 512) {                    // Wl
        int bb = b - nSplit;
        tsplit_block_h(Wl, Wlrt_h, Wlrt_l, 512, 1024, bb & 31, bb >> 5, tid);
    } else if (b < nSplit + 1024) {                   // Wr
        int bb = b - nSplit - 512;
        tsplit_block_h(Wr, Wlrt_h + 1024 * 512, Wlrt_l + 1024 * 512,
                       512, 1024, bb & 31, bb >> 5, tid);
    } else if (b < nSplit + 1536) {                   // W1
        int bb = b - nSplit - 1024;
        tsplit_block_h(W1, W1t_h, W1t_l, 1024, 512, bb & 15, bb >> 4, tid);
    } else if (b < nSplit + 1600) {                   // W2
        int bb = b - nSplit - 1536;
        tsplit_block_bf(W2, W2t_h, W2t_l, 512, 128, bb & 3, bb >> 2, tid);
    } else if (b < nSplit + 1616) {                   // Wc
        int bb = b - nSplit - 1600;
        tsplit_block_bf(Wc, Wct_h, Wct_l, 128, 100, bb & 3, bb >> 2, tid);
    } else if (b < nSplit + 1616 + nCount) {          // deg count (edges)
        int k = (b - nSplit - 1616) * 256 + tid;
        if (k < E) atomicAdd(&g_deg[dstA[k]], 1);
    } else {                                          // deg/cur init handled below
        int i = (b - nSplit - 1616 - nCount) * 256 + tid;
        if (i < n) g_cur[i] = 0;
    }
}

// deg must START at 1 (self-loop) before counting: separate tiny init first
__global__ void init_deg_kernel(int n) {
    int i = blockIdx.x * blockDim.x + threadIdx.x;
    if (i < n) g_deg[i] = 1;
}

// ============================================================================
// CSR build
// ============================================================================
__global__ __launch_bounds__(1024)
void scan_kernel(int n) {
    __shared__ int part[1024];
    int tid = threadIdx.x;
    int chunk = (n + 1023) >> 10;
    int beg = tid * chunk;
    int end = min(beg + chunk, n);
    int s = 0;
    for (int i = beg; i < end; i++) s += g_deg[i];
    part[tid] = s;
    __syncthreads();
    for (int d = 1; d < 1024; d <<= 1) {
        int v = part[tid];
        int a = (tid >= d) ? part[tid - d] : 0;
        __syncthreads();
        part[tid] = v + a;
        __syncthreads();
    }
    int run = (tid > 0) ? part[tid - 1] : 0;
    for (int i = beg; i < end; i++) { g_off[i] = run; run += g_deg[i]; }
    if (tid == 1023) g_off[n] = part[1023];
}
__global__ void fill_kernel(const int* __restrict__ src, const int* __restrict__ dst,
                            int E, int total) {
    int k = blockIdx.x * blockDim.x + threadIdx.x;
    if (k >= total) return;
    int d = (k < E) ? dst[k] : (k - E);
    int s = (k < E) ? src[k] : (k - E);
    int pos = atomicAdd(&g_cur[d], 1);
    int p = g_off[d] + pos;
    g_srcs[p] = s;
    g_dsts[p] = d;
}

// ============================================================================
// Edge scores over dst-sorted positions (fp32, validated structure)
// ============================================================================
__global__ __launch_bounds__(256)
void edge_e_kernel(const float* __restrict__ att, int total)
{
    int w = blockIdx.x * 8 + (threadIdx.x >> 5);
    if (w >= total) return;
    int lane = threadIdx.x & 31;
    int s = g_srcs[w];
    int d = g_dsts[w];
    const float4* xl4 = (const float4*)(g_xl + (size_t)s * HID);
    const float4* xr4 = (const float4*)(g_xr + (size_t)d * HID);
    const float4* at4 = (const float4*)att;
    float acc = 0.f;
#pragma unroll
    for (int j = 0; j < 8; j++) {
        int idx = lane + j * 32;
        float4 a = xl4[idx];
        float4 b = xr4[idx];
        float4 t = at4[idx];
        float v;
        v = a.x + b.x; v = (v > 0.f) ? v : NEG_SLOPE * v; acc = fmaf(v, t.x, acc);
        v = a.y + b.y; v = (v > 0.f) ? v : NEG_SLOPE * v; acc = fmaf(v, t.y, acc);
        v = a.z + b.z; v = (v > 0.f) ? v : NEG_SLOPE * v; acc = fmaf(v, t.z, acc);
        v = a.w + b.w; v = (v > 0.f) ? v : NEG_SLOPE * v; acc = fmaf(v, t.w, acc);
    }
#pragma unroll
    for (int o = 16; o > 0; o >>= 1) acc += __shfl_xor_sync(0xffffffffu, acc, o);
    if (lane == 0) g_e[w] = acc;
}

// ============================================================================
// Segment softmax + aggregation.  Pass 2: 2 edge-groups x 128 threads reading
// fp16 xl rows (uint4 = 8 halves per thread), fp32 accumulate, SMEM combine.
// ============================================================================
#define DEGCAP 1024
__global__ __launch_bounds__(256)
void aggregate_kernel(const float* __restrict__ conv_b)
{
    int node = blockIdx.x;
    int tid = threadIdx.x;
    int beg = g_off[node];
    int deg = g_off[node + 1] - beg;

    __shared__ float s_w[DEGCAP];
    __shared__ int   s_src[DEGCAP];
    __shared__ float red[256];
    __shared__ __align__(16) float sacc[HID];

    if (deg <= DEGCAP) {
        for (int j = tid; j < deg; j += 256) {
            s_w[j] = g_e[beg + j];
            s_src[j] = g_srcs[beg + j];
        }
        __syncthreads();
        float mx = -1e30f;
        for (int j = tid; j < deg; j += 256) mx = fmaxf(mx, s_w[j]);
        red[tid] = mx; __syncthreads();
        for (int o = 128; o > 0; o >>= 1) {
            if (tid < o) red[tid] = fmaxf(red[tid], red[tid + o]);
            __syncthreads();
        }
        float m = red[0];
        __syncthreads();
        for (int j = tid; j < deg; j += 256) s_w[j] = __expf(s_w[j] - m);
        float sl = 0.f;
        for (int j = tid; j < deg; j += 256) sl += s_w[j];
        red[tid] = sl; __syncthreads();
        for (int o = 128; o > 0; o >>= 1) {
            if (tid < o) red[tid] += red[tid + o];
            __syncthreads();
        }
        float ssum = red[0];
        __syncthreads();

        // ---- pass 2: group g handles edges j = g, g+2, ...; 8 els/thread ----
        const int g = tid >> 7;
        const int lt = tid & 127;
        float a[8];
#pragma unroll
        for (int i = 0; i < 8; i++) a[i] = 0.f;

        int j = g;
        for (; j + 2 < deg; j += 4) {
            float w0 = s_w[j], w1 = s_w[j + 2];
            uint4 v0 = ((const uint4*)(g_xlh + (size_t)s_src[j] * HID))[lt];
            uint4 v1 = ((const uint4*)(g_xlh + (size_t)s_src[j + 2] * HID))[lt];
            const __half2* p0 = (const __half2*)&v0;
            const __half2* p1 = (const __half2*)&v1;
#pragma unroll
            for (int q = 0; q < 4; q++) {
                float2 f0 = __half22float2(p0[q]);
                float2 f1 = __half22float2(p1[q]);
                a[q * 2 + 0] = fmaf(w0, f0.x, a[q * 2 + 0]);
                a[q * 2 + 1] = fmaf(w0, f0.y, a[q * 2 + 1]);
                a[q * 2 + 0] = fmaf(w1, f1.x, a[q * 2 + 0]);
                a[q * 2 + 1] = fmaf(w1, f1.y, a[q * 2 + 1]);
            }
        }
        for (; j < deg; j += 2) {
            float w0 = s_w[j];
            uint4 v0 = ((const uint4*)(g_xlh + (size_t)s_src[j] * HID))[lt];
            const __half2* p0 = (const __half2*)&v0;
#pragma unroll
            for (int q = 0; q < 4; q++) {
                float2 f0 = __half22float2(p0[q]);
                a[q * 2 + 0] = fmaf(w0, f0.x, a[q * 2 + 0]);
                a[q * 2 + 1] = fmaf(w0, f0.y, a[q * 2 + 1]);
            }
        }

        // combine groups
        if (g == 1) {
#pragma unroll
            for (int i = 0; i < 8; i++) sacc[lt * 8 + i] = a[i];
        }
        __syncthreads();
        if (g == 0) {
            float inv = 1.f / ssum;
            float4 cb0 = ((const float4*)conv_b)[lt * 2 + 0];
            float4 cb1 = ((const float4*)conv_b)[lt * 2 + 1];
            float o[8];
#pragma unroll
            for (int i = 0; i < 8; i++) a[i] += sacc[lt * 8 + i];
            o[0] = fmaxf(fmaf(a[0], inv, cb0.x), 0.f);
            o[1] = fmaxf(fmaf(a[1], inv, cb0.y), 0.f);
            o[2] = fmaxf(fmaf(a[2], inv, cb0.z), 0.f);
            o[3] = fmaxf(fmaf(a[3], inv, cb0.w), 0.f);
            o[4] = fmaxf(fmaf(a[4], inv, cb1.x), 0.f);
            o[5] = fmaxf(fmaf(a[5], inv, cb1.y), 0.f);
            o[6] = fmaxf(fmaf(a[6], inv, cb1.z), 0.f);
            o[7] = fmaxf(fmaf(a[7], inv, cb1.w), 0.f);
            uint4 pack;
            __half2* hp = (__half2*)&pack;
            hp[0] = __floats2half2_rn(o[0], o[1]);
            hp[1] = __floats2half2_rn(o[2], o[3]);
            hp[2] = __floats2half2_rn(o[4], o[5]);
            hp[3] = __floats2half2_rn(o[6], o[7]);
            ((uint4*)(g_hh + (size_t)node * HID))[lt] = pack;
        }
    } else {
        // fallback (deg > 1024): fp32 path
        float mx = -1e30f;
        for (int j = tid; j < deg; j += 256) mx = fmaxf(mx, g_e[beg + j]);
        red[tid] = mx; __syncthreads();
        for (int o = 128; o > 0; o >>= 1) {
            if (tid < o) red[tid] = fmaxf(red[tid], red[tid + o]);
            __syncthreads();
        }
        float m = red[0];
        __syncthreads();
        float sl = 0.f;
        for (int j = tid; j < deg; j += 256) sl += __expf(g_e[beg + j] - m);
        red[tid] = sl; __syncthreads();
        for (int o = 128; o > 0; o >>= 1) {
            if (tid < o) red[tid] += red[tid + o];
            __syncthreads();
        }
        float ssum = red[0];
        __syncthreads();
        float4 acc = make_float4(0.f, 0.f, 0.f, 0.f);
        for (int j = 0; j < deg; j++) {
            float wgt = __expf(g_e[beg + j] - m);
            const float4* row = (const float4*)(g_xl + (size_t)g_srcs[beg + j] * HID);
            float4 v = row[tid];
            acc.x = fmaf(wgt, v.x, acc.x);
            acc.y = fmaf(wgt, v.y, acc.y);
            acc.z = fmaf(wgt, v.z, acc.z);
            acc.w = fmaf(wgt, v.w, acc.w);
        }
        float inv = 1.f / ssum;
        float4 cb = ((const float4*)conv_b)[tid];
        float ox = fmaxf(fmaf(acc.x, inv, cb.x), 0.f);
        float oy = fmaxf(fmaf(acc.y, inv, cb.y), 0.f);
        float oz = fmaxf(fmaf(acc.z, inv, cb.z), 0.f);
        float ow = fmaxf(fmaf(acc.w, inv, cb.w), 0.f);
        __half2* hp = (__half2*)(g_hh + (size_t)node * HID + tid * 4);
        hp[0] = __floats2half2_rn(ox, oy);
        hp[1] = __floats2half2_rn(oz, ow);
    }
}

// ============================================================================
// launch
// ============================================================================
extern "C" void kernel_launch(void* const* d_in, const int* in_sizes, int n_in,
                              void* d_out, int out_size)
{
    const float* x   = (const float*)d_in[0];
    const int*   ei  = (const int*)d_in[1];
    const float* Wl  = (const float*)d_in[2];
    const float* bl  = (const float*)d_in[3];
    const float* Wr  = (const float*)d_in[4];
    const float* br  = (const float*)d_in[5];
    const float* att = (const float*)d_in[6];
    const float* cb  = (const float*)d_in[7];
    const float* W1  = (const float*)d_in[8];
    const float* b1  = (const float*)d_in[9];
    const float* W2  = (const float*)d_in[10];
    const float* b2  = (const float*)d_in[11];
    const float* Wc  = (const float*)d_in[12];
    const float* bc  = (const float*)d_in[13];

    const int n = in_sizes[0] / 512;
    const int E = in_sizes[1] / 2;
    const int total = E + n;
    const int* srcA = ei;
    const int* dstA = ei + E;

    float *xl, *xr;
    __half *xlh, *xh, *hh, *Wlrt_h, *Wlrt_l, *W1t_h, *W1t_l;
    __nv_bfloat16 *h1h, *h1l, *h2h, *h2l, *W2t_h, *W2t_l, *Wct_h, *Wct_l;
    cudaGetSymbolAddress((void**)&xl,  g_xl);
    cudaGetSymbolAddress((void**)&xr,  g_xr);
    cudaGetSymbolAddress((void**)&xlh, g_xlh);
    cudaGetSymbolAddress((void**)&xh,  g_xh);
    cudaGetSymbolAddress((void**)&hh,  g_hh);
    cudaGetSymbolAddress((void**)&h1h, g_h1h);
    cudaGetSymbolAddress((void**)&h1l, g_h1l);
    cudaGetSymbolAddress((void**)&h2h, g_h2h);
    cudaGetSymbolAddress((void**)&h2l, g_h2l);
    cudaGetSymbolAddress((void**)&Wlrt_h, g_Wlrt_h);
    cudaGetSymbolAddress((void**)&Wlrt_l, g_Wlrt_l);
    cudaGetSymbolAddress((void**)&W1t_h, g_W1t_h);
    cudaGetSymbolAddress((void**)&W1t_l, g_W1t_l);
    cudaGetSymbolAddress((void**)&W2t_h, g_W2t_h);
    cudaGetSymbolAddress((void**)&W2t_l, g_W2t_l);
    cudaGetSymbolAddress((void**)&Wct_h, g_Wct_h);
    cudaGetSymbolAddress((void**)&Wct_l, g_Wct_l);
    float* out = (float*)d_out;

    cudaFuncSetAttribute(gemm_mma_h<false, true, false, true>,
                         cudaFuncAttributeMaxDynamicSharedMemorySize, GSMEM_H);
    cudaFuncSetAttribute(gemm_mma_h<true, false, true, false>,
                         cudaFuncAttributeMaxDynamicSharedMemorySize, GSMEM_H);
    cudaFuncSetAttribute(gemm_mma<true, false, true>,
                         cudaFuncAttributeMaxDynamicSharedMemorySize, GSMEM);
    cudaFuncSetAttribute(gemm_mma<false, true, false>,
                         cudaFuncAttributeMaxDynamicSharedMemorySize, GSMEM);

    // deg = 1 (self-loop) must precede the counting inside prep
    init_deg_kernel<<<(n + 255) / 256, 256>>>(n);

    // single prep launch: split_x + 5 weight splits + edge count + cur init
    int nSplit = (n * 128 + 255) / 256;
    int nCount = (E + 255) / 256;
    int nInit  = (n + 255) / 256;
    prep_kernel<<<nSplit + 1616 + nCount + nInit, 256>>>(
        x, dstA, Wl, Wr, W1, W2, Wc,
        Wlrt_h, Wlrt_l, W1t_h, W1t_l, W2t_h, W2t_l, Wct_h, Wct_l,
        xh, n, E, nSplit, nCount);

    // combined xl|xr transform: fp16 2-term; xl also written as fp16
    dim3 gx(2048 / 128, (n + 127) / 128);
    gemm_mma_h<false, true, false, true><<<gx, 256, GSMEM_H>>>(
        xh, Wlrt_h, Wlrt_l, bl, br, xl, xr, xlh, nullptr, nullptr, n, 2048, 512);

    scan_kernel<<<1, 1024>>>(n);
    fill_kernel<<<(total + 255) / 256, 256>>>(srcA, dstA, E, total);

    edge_e_kernel<<<(total + 7) / 8, 256>>>(att, total);
    aggregate_kernel<<<n, 256>>>(cb);

    // MLP head: W1 fp16 2-term; W2/Wc bf16 3-term
    dim3 g1(512 / 128, (n + 127) / 128);
    gemm_mma_h<true, false, true, false><<<g1, 256, GSMEM_H>>>(
        hh, W1t_h, W1t_l, b1, nullptr, nullptr, nullptr, nullptr, h1h, h1l, n, 512, 1024);
    dim3 g2(1, (n + 127) / 128);
    gemm_mma<true, false, true><<<g2, 256, GSMEM>>>(
        h1h, h1l, W2t_h, W2t_l, b2, nullptr, h2h, h2l, n, 128, 512);
    dim3 g3(1, (n + 127) / 128);
    gemm_mma<false, true, false><<<g3, 256, GSMEM>>>(
        h2h, h2l, Wct_h, Wct_l, bc, out, nullptr, nullptr, n, 100, 128);
}

// round 16
// speedup vs baseline: 1.0356x; 1.0356x over previous
#include <cuda_runtime.h>
#include <cuda_bf16.h>
#include <cuda_fp16.h>
#include <cstdint>

#define HID 1024
#define NEG_SLOPE 0.2f

static const int NMAX = 10240;
static const int EMAX = 163840;
#define TMAX (EMAX + NMAX)

// ---------------- scratch (static device globals) ----------------
__device__ __align__(16) float g_xl[(size_t)NMAX * HID];
__device__ __align__(16) float g_xr[(size_t)NMAX * HID];
__device__ __align__(16) float g_e [TMAX];
__device__ int   g_deg[NMAX];          // zero at start of every call (self-cleaning)
__device__ int   g_cur[NMAX];          // zeroed by scan before fill uses it
__device__ int   g_off[NMAX + 1];
__device__ int   g_srcs[TMAX];
__device__ int   g_dsts[TMAX];

// fp16 activations (2-term GEMM path)
__device__ __align__(16) __half g_xh[(size_t)NMAX * 512];
__device__ __align__(16) __half g_hh[(size_t)NMAX * HID];
// bf16 hi/lo activations (3-term path for W2/Wc)
__device__ __align__(16) __nv_bfloat16 g_h1h[(size_t)NMAX * 512];
__device__ __align__(16) __nv_bfloat16 g_h1l[(size_t)NMAX * 512];
__device__ __align__(16) __nv_bfloat16 g_h2h[(size_t)NMAX * 128];
__device__ __align__(16) __nv_bfloat16 g_h2l[(size_t)NMAX * 128];

// transposed + split weights: Wt[n][k]
__device__ __align__(16) __half g_Wlrt_h[2048 * 512], g_Wlrt_l[2048 * 512];
__device__ __align__(16) __half g_W1t_h[512 * 1024],  g_W1t_l[512 * 1024];
__device__ __align__(16) __nv_bfloat16 g_W2t_h[128 * 512], g_W2t_l[128 * 512];
__device__ __align__(16) __nv_bfloat16 g_Wct_h[112 * 128], g_Wct_l[112 * 128];

// ---------------- PTX helpers ----------------
__device__ __forceinline__ uint32_t smem_u32(const void* p) {
    uint32_t a;
    asm("{ .reg .u64 t; cvta.to.shared.u64 t, %1; cvt.u32.u64 %0, t; }"
        : "=r"(a) : "l"(p));
    return a;
}
__device__ __forceinline__ void cp16(uint32_t saddr, const void* gaddr, int srcsize) {
    asm volatile("cp.async.cg.shared.global [%0], [%1], 16, %2;"
                 :: "r"(saddr), "l"(gaddr), "r"(srcsize) : "memory");
}
#define CP_COMMIT() asm volatile("cp.async.commit_group;" ::: "memory")
#define CP_WAIT(n)  asm volatile("cp.async.wait_group %0;" :: "n"(n) : "memory")

__device__ __forceinline__ void ldsm4(uint32_t& r0, uint32_t& r1, uint32_t& r2,
                                      uint32_t& r3, uint32_t a) {
    asm volatile("ldmatrix.sync.aligned.m8n8.x4.shared.b16 {%0,%1,%2,%3}, [%4];"
                 : "=r"(r0), "=r"(r1), "=r"(r2), "=r"(r3) : "r"(a));
}
__device__ __forceinline__ void mma_bf16(float* d, const uint32_t* a,
                                         uint32_t b0, uint32_t b1) {
    asm volatile(
        "mma.sync.aligned.m16n8k16.row.col.f32.bf16.bf16.f32 "
        "{%0,%1,%2,%3}, {%4,%5,%6,%7}, {%8,%9}, {%0,%1,%2,%3};"
        : "+f"(d[0]), "+f"(d[1]), "+f"(d[2]), "+f"(d[3])
        : "r"(a[0]), "r"(a[1]), "r"(a[2]), "r"(a[3]), "r"(b0), "r"(b1));
}
__device__ __forceinline__ void mma_f16(float* d, const uint32_t* a,
                                        uint32_t b0, uint32_t b1) {
    asm volatile(
        "mma.sync.aligned.m16n8k16.row.col.f32.f16.f16.f32 "
        "{%0,%1,%2,%3}, {%4,%5,%6,%7}, {%8,%9}, {%0,%1,%2,%3};"
        : "+f"(d[0]), "+f"(d[1]), "+f"(d[2]), "+f"(d[3])
        : "r"(a[0]), "r"(a[1]), "r"(a[2]), "r"(a[3]), "r"(b0), "r"(b1));
}

#define TILE_B   8192

__device__ __forceinline__ void fill_tile_async(
    uint32_t dst, const void* __restrict__ src2B,
    int rowbase, int limit, int K, int k0, int tid)
{
    int fr = tid >> 2;
    int fc = tid & 3;
#pragma unroll
    for (int it = 0; it < 2; it++) {
        int row = fr + it * 64;
        int grow = rowbase + row;
        uint32_t saddr = dst + row * 64 + ((fc ^ ((row >> 1) & 3)) * 16);
        const char* g = (const char*)src2B + ((size_t)grow * K + k0 + fc * 8) * 2;
        cp16(saddr, g, (grow < limit) ? 16 : 0);
    }
}

// ============================================================================
// bf16 3-term GEMM (used for W2, Wc)
// ============================================================================
#define STAGE_B  (4 * TILE_B)
#define GSMEM    (2 * STAGE_B)

template <bool RELU, bool WF32, bool WBF16>
__global__ __launch_bounds__(256, 1)
void gemm_mma(const __nv_bfloat16* __restrict__ Ah, const __nv_bfloat16* __restrict__ Al,
              const __nv_bfloat16* __restrict__ Bh, const __nv_bfloat16* __restrict__ Bl,
              const float* __restrict__ bias,
              float* __restrict__ C,
              __nv_bfloat16* __restrict__ Ch, __nv_bfloat16* __restrict__ Cl,
              int M, int Nn, int K)
{
    extern __shared__ char smem[];
    const uint32_t sb = smem_u32(smem);
    const int tid = threadIdx.x;
    const int wid = tid >> 5;
    const int lane = tid & 31;
    const int row0 = blockIdx.y * 128;
    const int col0 = blockIdx.x * 128;
    const int wm0 = (wid & 3) * 32;
    const int wn0 = (wid >> 2) * 64;

    float acc[2][8][4];
#pragma unroll
    for (int i = 0; i < 2; i++)
#pragma unroll
        for (int j = 0; j < 8; j++)
#pragma unroll
            for (int k = 0; k < 4; k++) acc[i][j][k] = 0.f;

    uint32_t aoff[2][2], boff[4][2];
#pragma unroll
    for (int mt = 0; mt < 2; mt++) {
        int arow = wm0 + mt * 16 + (lane & 15);
        int hi = lane >> 4;
#pragma unroll
        for (int s = 0; s < 2; s++) {
            int chunk = s * 2 + hi;
            aoff[mt][s] = arow * 64 + ((chunk ^ ((arow >> 1) & 3)) * 16);
        }
    }
#pragma unroll
    for (int bt = 0; bt < 4; bt++) {
        int brow = wn0 + bt * 16 + (lane & 7) + ((lane >> 4) & 1) * 8;
        int hi = (lane >> 3) & 1;
#pragma unroll
        for (int s = 0; s < 2; s++) {
            int chunk = s * 2 + hi;
            boff[bt][s] = brow * 64 + ((chunk ^ ((brow >> 1) & 3)) * 16);
        }
    }

    const int nC = K / 32;
    {
        uint32_t st = sb;
        fill_tile_async(st + 0 * TILE_B, Ah, row0, M,  K, 0, tid);
        fill_tile_async(st + 1 * TILE_B, Al, row0, M,  K, 0, tid);
        fill_tile_async(st + 2 * TILE_B, Bh, col0, Nn, K, 0, tid);
        fill_tile_async(st + 3 * TILE_B, Bl, col0, Nn, K, 0, tid);
        CP_COMMIT();
    }

    for (int c = 0; c < nC; c++) {
        const uint32_t st = sb + (c & 1) * STAGE_B;
        if (c + 1 < nC) {
            uint32_t nx = sb + ((c + 1) & 1) * STAGE_B;
            int k0 = (c + 1) * 32;
            fill_tile_async(nx + 0 * TILE_B, Ah, row0, M,  K, k0, tid);
            fill_tile_async(nx + 1 * TILE_B, Al, row0, M,  K, k0, tid);
            fill_tile_async(nx + 2 * TILE_B, Bh, col0, Nn, K, k0, tid);
            fill_tile_async(nx + 3 * TILE_B, Bl, col0, Nn, K, k0, tid);
            CP_COMMIT();
            CP_WAIT(1);
        } else {
            CP_WAIT(0);
        }
        __syncthreads();

#pragma unroll
        for (int s = 0; s < 2; s++) {
            uint32_t ah[2][4], al[2][4], bh[4][4], bl[4][4];
#pragma unroll
            for (int mt = 0; mt < 2; mt++) {
                ldsm4(ah[mt][0], ah[mt][1], ah[mt][2], ah[mt][3],
                      st + 0 * TILE_B + aoff[mt][s]);
                ldsm4(al[mt][0], al[mt][1], al[mt][2], al[mt][3],
                      st + 1 * TILE_B + aoff[mt][s]);
            }
#pragma unroll
            for (int bt = 0; bt < 4; bt++) {
                ldsm4(bh[bt][0], bh[bt][1], bh[bt][2], bh[bt][3],
                      st + 2 * TILE_B + boff[bt][s]);
                ldsm4(bl[bt][0], bl[bt][1], bl[bt][2], bl[bt][3],
                      st + 3 * TILE_B + boff[bt][s]);
            }
#pragma unroll
            for (int mt = 0; mt < 2; mt++) {
#pragma unroll
                for (int bt = 0; bt < 4; bt++) {
                    mma_bf16(acc[mt][2 * bt + 0], ah[mt], bh[bt][0], bh[bt][1]);
                    mma_bf16(acc[mt][2 * bt + 1], ah[mt], bh[bt][2], bh[bt][3]);
                    mma_bf16(acc[mt][2 * bt + 0], ah[mt], bl[bt][0], bl[bt][1]);
                    mma_bf16(acc[mt][2 * bt + 1], ah[mt], bl[bt][2], bl[bt][3]);
                    mma_bf16(acc[mt][2 * bt + 0], al[mt], bh[bt][0], bh[bt][1]);
                    mma_bf16(acc[mt][2 * bt + 1], al[mt], bh[bt][2], bh[bt][3]);
                }
            }
        }
        __syncthreads();
    }

#pragma unroll
    for (int mt = 0; mt < 2; mt++) {
#pragma unroll
        for (int nt = 0; nt < 8; nt++) {
            int col = col0 + wn0 + nt * 8 + (lane & 3) * 2;
            if (col >= Nn) continue;
            float bx = bias[col], by = bias[col + 1];
#pragma unroll
            for (int half = 0; half < 2; half++) {
                int grow = row0 + wm0 + mt * 16 + (lane >> 2) + half * 8;
                if (grow >= M) continue;
                float ox = acc[mt][nt][half * 2 + 0] + bx;
                float oy = acc[mt][nt][half * 2 + 1] + by;
                if (RELU) { ox = fmaxf(ox, 0.f); oy = fmaxf(oy, 0.f); }
                size_t idx = (size_t)grow * Nn + col;
                if (WF32) {
                    *(float2*)(C + idx) = make_float2(ox, oy);
                }
                if (WBF16) {
                    __nv_bfloat16 hx = __float2bfloat16(ox);
                    __nv_bfloat16 hy = __float2bfloat16(oy);
                    *(__nv_bfloat162*)(Ch + idx) = __nv_bfloat162(hx, hy);
                    *(__nv_bfloat162*)(Cl + idx) = __floats2bfloat162_rn(
                        ox - __bfloat162float(hx), oy - __bfloat162float(hy));
                }
            }
        }
    }
}

// ============================================================================
// fp16 2-term GEMM (A single fp16, B hi/lo)
// ============================================================================
#define STAGE_H  (3 * TILE_B)
#define GSMEM_H  (2 * STAGE_H)

template <bool RELU, bool WF32, bool WBF16, bool SPLITC>
__global__ __launch_bounds__(256, 1)
void gemm_mma_h(const __half* __restrict__ Ah,
                const __half* __restrict__ Bh, const __half* __restrict__ Bl,
                const float* __restrict__ bias, const float* __restrict__ bias2,
                float* __restrict__ C, float* __restrict__ C2,
                __nv_bfloat16* __restrict__ Chb, __nv_bfloat16* __restrict__ Clb,
                int M, int Nn, int K)
{
    extern __shared__ char smem[];
    const uint32_t sb = smem_u32(smem);
    const int tid = threadIdx.x;
    const int wid = tid >> 5;
    const int lane = tid & 31;
    const int row0 = blockIdx.y * 128;
    const int col0 = blockIdx.x * 128;
    const int wm0 = (wid & 3) * 32;
    const int wn0 = (wid >> 2) * 64;

    float acc[2][8][4];
#pragma unroll
    for (int i = 0; i < 2; i++)
#pragma unroll
        for (int j = 0; j < 8; j++)
#pragma unroll
            for (int k = 0; k < 4; k++) acc[i][j][k] = 0.f;

    uint32_t aoff[2][2], boff[4][2];
#pragma unroll
    for (int mt = 0; mt < 2; mt++) {
        int arow = wm0 + mt * 16 + (lane & 15);
        int hi = lane >> 4;
#pragma unroll
        for (int s = 0; s < 2; s++) {
            int chunk = s * 2 + hi;
            aoff[mt][s] = arow * 64 + ((chunk ^ ((arow >> 1) & 3)) * 16);
        }
    }
#pragma unroll
    for (int bt = 0; bt < 4; bt++) {
        int brow = wn0 + bt * 16 + (lane & 7) + ((lane >> 4) & 1) * 8;
        int hi = (lane >> 3) & 1;
#pragma unroll
        for (int s = 0; s < 2; s++) {
            int chunk = s * 2 + hi;
            boff[bt][s] = brow * 64 + ((chunk ^ ((brow >> 1) & 3)) * 16);
        }
    }

    const int nC = K / 32;
    {
        uint32_t st = sb;
        fill_tile_async(st + 0 * TILE_B, Ah, row0, M,  K, 0, tid);
        fill_tile_async(st + 1 * TILE_B, Bh, col0, Nn, K, 0, tid);
        fill_tile_async(st + 2 * TILE_B, Bl, col0, Nn, K, 0, tid);
        CP_COMMIT();
    }

    for (int c = 0; c < nC; c++) {
        const uint32_t st = sb + (c & 1) * STAGE_H;
        if (c + 1 < nC) {
            uint32_t nx = sb + ((c + 1) & 1) * STAGE_H;
            int k0 = (c + 1) * 32;
            fill_tile_async(nx + 0 * TILE_B, Ah, row0, M,  K, k0, tid);
            fill_tile_async(nx + 1 * TILE_B, Bh, col0, Nn, K, k0, tid);
            fill_tile_async(nx + 2 * TILE_B, Bl, col0, Nn, K, k0, tid);
            CP_COMMIT();
            CP_WAIT(1);
        } else {
            CP_WAIT(0);
        }
        __syncthreads();

#pragma unroll
        for (int s = 0; s < 2; s++) {
            uint32_t ah[2][4], bh[4][4], bl[4][4];
#pragma unroll
            for (int mt = 0; mt < 2; mt++) {
                ldsm4(ah[mt][0], ah[mt][1], ah[mt][2], ah[mt][3],
                      st + 0 * TILE_B + aoff[mt][s]);
            }
#pragma unroll
            for (int bt = 0; bt < 4; bt++) {
                ldsm4(bh[bt][0], bh[bt][1], bh[bt][2], bh[bt][3],
                      st + 1 * TILE_B + boff[bt][s]);
                ldsm4(bl[bt][0], bl[bt][1], bl[bt][2], bl[bt][3],
                      st + 2 * TILE_B + boff[bt][s]);
            }
#pragma unroll
            for (int mt = 0; mt < 2; mt++) {
#pragma unroll
                for (int bt = 0; bt < 4; bt++) {
                    mma_f16(acc[mt][2 * bt + 0], ah[mt], bh[bt][0], bh[bt][1]);
                    mma_f16(acc[mt][2 * bt + 1], ah[mt], bh[bt][2], bh[bt][3]);
                    mma_f16(acc[mt][2 * bt + 0], ah[mt], bl[bt][0], bl[bt][1]);
                    mma_f16(acc[mt][2 * bt + 1], ah[mt], bl[bt][2], bl[bt][3]);
                }
            }
        }
        __syncthreads();
    }

#pragma unroll
    for (int mt = 0; mt < 2; mt++) {
#pragma unroll
        for (int nt = 0; nt < 8; nt++) {
            int col = col0 + wn0 + nt * 8 + (lane & 3) * 2;
            if (col >= Nn) continue;
            const float* bp = bias;
            float* Cp = C;
            int ccol = col;
            int cw = Nn;
            if (SPLITC) {
                cw = 1024;
                if (col >= 1024) { bp = bias2; Cp = C2; ccol = col - 1024; }
            }
            float bx = bp[ccol], by = bp[ccol + 1];
#pragma unroll
            for (int half = 0; half < 2; half++) {
                int grow = row0 + wm0 + mt * 16 + (lane >> 2) + half * 8;
                if (grow >= M) continue;
                float ox = acc[mt][nt][half * 2 + 0] + bx;
                float oy = acc[mt][nt][half * 2 + 1] + by;
                if (RELU) { ox = fmaxf(ox, 0.f); oy = fmaxf(oy, 0.f); }
                if (WF32) {
                    *(float2*)(Cp + (size_t)grow * cw + ccol) = make_float2(ox, oy);
                }
                if (WBF16) {
                    size_t idx = (size_t)grow * Nn + col;
                    __nv_bfloat16 hx = __float2bfloat16(ox);
                    __nv_bfloat16 hy = __float2bfloat16(oy);
                    *(__nv_bfloat162*)(Chb + idx) = __nv_bfloat162(hx, hy);
                    *(__nv_bfloat162*)(Clb + idx) = __floats2bfloat162_rn(
                        ox - __bfloat162float(hx), oy - __bfloat162float(hy));
                }
            }
        }
    }
}

// ============================================================================
// Prep (single launch: split_x + all weight splits + edge count)
// g_deg starts zero (static init on first call; scan re-zeroes every call).
// ============================================================================
__device__ __forceinline__ void tsplit_block_bf(
    const float* __restrict__ W, __nv_bfloat16* __restrict__ th,
    __nv_bfloat16* __restrict__ tl, int K, int N, int bx, int by, int tid)
{
    __shared__ float t[32][33];
    int k0 = by * 32, n0 = bx * 32;
    int tx = tid & 31, ty = tid >> 5;
#pragma unroll
    for (int i = 0; i < 4; i++) {
        int k = k0 + ty + i * 8;
        t[ty + i * 8][tx] = (k < K && n0 + tx < N) ? W[(size_t)k * N + n0 + tx] : 0.f;
    }
    __syncthreads();
#pragma unroll
    for (int i = 0; i < 4; i++) {
        int n = n0 + ty + i * 8;
        int k = k0 + tx;
        if (n < N && k < K) {
            float v = t[tx][ty + i * 8];
            __nv_bfloat16 hb = __float2bfloat16(v);
            th[(size_t)n * K + k] = hb;
            tl[(size_t)n * K + k] = __float2bfloat16(v - __bfloat162float(hb));
        }
    }
}
__device__ __forceinline__ void tsplit_block_h(
    const float* __restrict__ W, __half* __restrict__ th,
    __half* __restrict__ tl, int K, int N, int bx, int by, int tid)
{
    __shared__ float t[32][33];
    int k0 = by * 32, n0 = bx * 32;
    int tx = tid & 31, ty = tid >> 5;
#pragma unroll
    for (int i = 0; i < 4; i++) {
        int k = k0 + ty + i * 8;
        t[ty + i * 8][tx] = (k < K && n0 + tx < N) ? W[(size_t)k * N + n0 + tx] : 0.f;
    }
    __syncthreads();
#pragma unroll
    for (int i = 0; i < 4; i++) {
        int n = n0 + ty + i * 8;
        int k = k0 + tx;
        if (n < N && k < K) {
            float v = t[tx][ty + i * 8];
            __half hb = __float2half_rn(v);
            th[(size_t)n * K + k] = hb;
            tl[(size_t)n * K + k] = __float2half_rn(v - __half2float(hb));
        }
    }
}

__global__ __launch_bounds__(256)
void prep_kernel(const float* __restrict__ x, const int* __restrict__ dstA,
                 const float* __restrict__ Wl, const float* __restrict__ Wr,
                 const float* __restrict__ W1, const float* __restrict__ W2,
                 const float* __restrict__ Wc,
                 __half* Wlrt_h, __half* Wlrt_l,
                 __half* W1t_h, __half* W1t_l,
                 __nv_bfloat16* W2t_h, __nv_bfloat16* W2t_l,
                 __nv_bfloat16* Wct_h, __nv_bfloat16* Wct_l,
                 __half* xh,
                 int n, int E, int nSplit)
{
    int b = blockIdx.x;
    int tid = threadIdx.x;
    if (b < nSplit) {                                 // x -> fp16
        int i = b * 256 + tid;
        int n4 = n * 128;
        if (i < n4) {
            float4 v = ((const float4*)x)[i];
            __half2* h2 = (__half2*)xh;
            h2[i * 2 + 0] = __floats2half2_rn(v.x, v.y);
            h2[i * 2 + 1] = __floats2half2_rn(v.z, v.w);
        }
    } else if (b < nSplit + 512) {
        int bb = b - nSplit;
        tsplit_block_h(Wl, Wlrt_h, Wlrt_l, 512, 1024, bb & 31, bb >> 5, tid);
    } else if (b < nSplit + 1024) {
        int bb = b - nSplit - 512;
        tsplit_block_h(Wr, Wlrt_h + 1024 * 512, Wlrt_l + 1024 * 512,
                       512, 1024, bb & 31, bb >> 5, tid);
    } else if (b < nSplit + 1536) {
        int bb = b - nSplit - 1024;
        tsplit_block_h(W1, W1t_h, W1t_l, 1024, 512, bb & 15, bb >> 4, tid);
    } else if (b < nSplit + 1600) {
        int bb = b - nSplit - 1536;
        tsplit_block_bf(W2, W2t_h, W2t_l, 512, 128, bb & 3, bb >> 2, tid);
    } else if (b < nSplit + 1616) {
        int bb = b - nSplit - 1600;
        tsplit_block_bf(Wc, Wct_h, Wct_l, 128, 100, bb & 3, bb >> 2, tid);
    } else {                                          // edge count (deg zero-based)
        int k = (b - nSplit - 1616) * 256 + tid;
        if (k < E) atomicAdd(&g_deg[dstA[k]], 1);
    }
}

// ============================================================================
// CSR scan (shuffle-based) — adds +1 self-loop per node; zeroes deg/cur.
// ============================================================================
__global__ __launch_bounds__(1024)
void scan_kernel(int n) {
    __shared__ int warpsum[32];
    int tid = threadIdx.x;
    int lane = tid & 31, wrp = tid >> 5;
    int chunk = (n + 1023) >> 10;
    int beg = min(tid * chunk, n);
    int end = min(beg + chunk, n);
    int s = 0;
    for (int i = beg; i < end; i++) s += g_deg[i] + 1;
    int v = s;
#pragma unroll
    for (int o = 1; o < 32; o <<= 1) {
        int t = __shfl_up_sync(0xffffffffu, v, o);
        if (lane >= o) v += t;
    }
    if (lane == 31) warpsum[wrp] = v;
    __syncthreads();
    if (wrp == 0) {
        int w = warpsum[lane];
#pragma unroll
        for (int o = 1; o < 32; o <<= 1) {
            int t = __shfl_up_sync(0xffffffffu, w, o);
            if (lane >= o) w += t;
        }
        warpsum[lane] = w;
    }
    __syncthreads();
    int run = v - s + ((wrp > 0) ? warpsum[wrp - 1] : 0);
    for (int i = beg; i < end; i++) {
        g_off[i] = run;
        run += g_deg[i] + 1;
        g_deg[i] = 0;      // self-clean for next call
        g_cur[i] = 0;      // reset before this call's fill
    }
    if (tid == 1023) g_off[n] = warpsum[31];
}

__global__ void fill_kernel(const int* __restrict__ src, const int* __restrict__ dst,
                            int E, int total) {
    int k = blockIdx.x * blockDim.x + threadIdx.x;
    if (k >= total) return;
    int d = (k < E) ? dst[k] : (k - E);
    int s = (k < E) ? src[k] : (k - E);
    int pos = atomicAdd(&g_cur[d], 1);
    int p = g_off[d] + pos;
    g_srcs[p] = s;
    g_dsts[p] = d;
}

// ============================================================================
// Edge scores over dst-sorted positions (fp32, validated structure)
// ============================================================================
__global__ __launch_bounds__(256)
void edge_e_kernel(const float* __restrict__ att, int total)
{
    int w = blockIdx.x * 8 + (threadIdx.x >> 5);
    if (w >= total) return;
    int lane = threadIdx.x & 31;
    int s = g_srcs[w];
    int d = g_dsts[w];
    const float4* xl4 = (const float4*)(g_xl + (size_t)s * HID);
    const float4* xr4 = (const float4*)(g_xr + (size_t)d * HID);
    const float4* at4 = (const float4*)att;
    float acc = 0.f;
#pragma unroll
    for (int j = 0; j < 8; j++) {
        int idx = lane + j * 32;
        float4 a = xl4[idx];
        float4 b = xr4[idx];
        float4 t = at4[idx];
        float v;
        v = a.x + b.x; v = (v > 0.f) ? v : NEG_SLOPE * v; acc = fmaf(v, t.x, acc);
        v = a.y + b.y; v = (v > 0.f) ? v : NEG_SLOPE * v; acc = fmaf(v, t.y, acc);
        v = a.z + b.z; v = (v > 0.f) ? v : NEG_SLOPE * v; acc = fmaf(v, t.z, acc);
        v = a.w + b.w; v = (v > 0.f) ? v : NEG_SLOPE * v; acc = fmaf(v, t.w, acc);
    }
#pragma unroll
    for (int o = 16; o > 0; o >>= 1) acc += __shfl_xor_sync(0xffffffffu, acc, o);
    if (lane == 0) g_e[w] = acc;
}

// ============================================================================
// Segment softmax + aggregation (round-12 fp32 version; writes fp16 h)
// ============================================================================
#define DEGCAP 1024
__global__ __launch_bounds__(256)
void aggregate_kernel(const float* __restrict__ conv_b)
{
    int node = blockIdx.x;
    int tid = threadIdx.x;
    int beg = g_off[node];
    int deg = g_off[node + 1] - beg;

    __shared__ float s_w[DEGCAP];
    __shared__ int   s_src[DEGCAP];
    __shared__ float red[256];

    float m, ssum;
    float4 acc = make_float4(0.f, 0.f, 0.f, 0.f);

    if (deg <= DEGCAP) {
        for (int j = tid; j < deg; j += 256) {
            s_w[j] = g_e[beg + j];
            s_src[j] = g_srcs[beg + j];
        }
        __syncthreads();
        float mx = -1e30f;
        for (int j = tid; j < deg; j += 256) mx = fmaxf(mx, s_w[j]);
        red[tid] = mx; __syncthreads();
        for (int o = 128; o > 0; o >>= 1) {
            if (tid < o) red[tid] = fmaxf(red[tid], red[tid + o]);
            __syncthreads();
        }
        m = red[0];
        __syncthreads();
        for (int j = tid; j < deg; j += 256) s_w[j] = __expf(s_w[j] - m);
        float sl = 0.f;
        for (int j = tid; j < deg; j += 256) sl += s_w[j];
        red[tid] = sl; __syncthreads();
        for (int o = 128; o > 0; o >>= 1) {
            if (tid < o) red[tid] += red[tid + o];
            __syncthreads();
        }
        ssum = red[0];
        __syncthreads();
        int j = 0;
        for (; j + 3 < deg; j += 4) {
            float w0 = s_w[j + 0], w1 = s_w[j + 1], w2 = s_w[j + 2], w3 = s_w[j + 3];
            const float4* r0 = (const float4*)(g_xl + (size_t)s_src[j + 0] * HID);
            const float4* r1 = (const float4*)(g_xl + (size_t)s_src[j + 1] * HID);
            const float4* r2 = (const float4*)(g_xl + (size_t)s_src[j + 2] * HID);
            const float4* r3 = (const float4*)(g_xl + (size_t)s_src[j + 3] * HID);
            float4 v0 = r0[tid], v1 = r1[tid], v2 = r2[tid], v3 = r3[tid];
            acc.x = fmaf(w0, v0.x, acc.x); acc.y = fmaf(w0, v0.y, acc.y);
            acc.z = fmaf(w0, v0.z, acc.z); acc.w = fmaf(w0, v0.w, acc.w);
            acc.x = fmaf(w1, v1.x, acc.x); acc.y = fmaf(w1, v1.y, acc.y);
            acc.z = fmaf(w1, v1.z, acc.z); acc.w = fmaf(w1, v1.w, acc.w);
            acc.x = fmaf(w2, v2.x, acc.x); acc.y = fmaf(w2, v2.y, acc.y);
            acc.z = fmaf(w2, v2.z, acc.z); acc.w = fmaf(w2, v2.w, acc.w);
            acc.x = fmaf(w3, v3.x, acc.x); acc.y = fmaf(w3, v3.y, acc.y);
            acc.z = fmaf(w3, v3.z, acc.z); acc.w = fmaf(w3, v3.w, acc.w);
        }
        for (; j < deg; j++) {
            float wgt = s_w[j];
            const float4* row = (const float4*)(g_xl + (size_t)s_src[j] * HID);
            float4 v = row[tid];
            acc.x = fmaf(wgt, v.x, acc.x);
            acc.y = fmaf(wgt, v.y, acc.y);
            acc.z = fmaf(wgt, v.z, acc.z);
            acc.w = fmaf(wgt, v.w, acc.w);
        }
    } else {
        float mx = -1e30f;
        for (int j = tid; j < deg; j += 256) mx = fmaxf(mx, g_e[beg + j]);
        red[tid] = mx; __syncthreads();
        for (int o = 128; o > 0; o >>= 1) {
            if (tid < o) red[tid] = fmaxf(red[tid], red[tid + o]);
            __syncthreads();
        }
        m = red[0];
        __syncthreads();
        float sl = 0.f;
        for (int j = tid; j < deg; j += 256) sl += __expf(g_e[beg + j] - m);
        red[tid] = sl; __syncthreads();
        for (int o = 128; o > 0; o >>= 1) {
            if (tid < o) red[tid] += red[tid + o];
            __syncthreads();
        }
        ssum = red[0];
        __syncthreads();
        for (int j = 0; j < deg; j++) {
            float wgt = __expf(g_e[beg + j] - m);
            const float4* row = (const float4*)(g_xl + (size_t)g_srcs[beg + j] * HID);
            float4 v = row[tid];
            acc.x = fmaf(wgt, v.x, acc.x);
            acc.y = fmaf(wgt, v.y, acc.y);
            acc.z = fmaf(wgt, v.z, acc.z);
            acc.w = fmaf(wgt, v.w, acc.w);
        }
    }

    float inv = 1.f / ssum;
    float4 cb = ((const float4*)conv_b)[tid];
    float ox = fmaxf(fmaf(acc.x, inv, cb.x), 0.f);
    float oy = fmaxf(fmaf(acc.y, inv, cb.y), 0.f);
    float oz = fmaxf(fmaf(acc.z, inv, cb.z), 0.f);
    float ow = fmaxf(fmaf(acc.w, inv, cb.w), 0.f);
    __half2* hp = (__half2*)(g_hh + (size_t)node * HID + tid * 4);
    hp[0] = __floats2half2_rn(ox, oy);
    hp[1] = __floats2half2_rn(oz, ow);
}

// ============================================================================
// launch — with capture-safe stream fork/join (CSR chain under xl|xr GEMM)
// ============================================================================
extern "C" void kernel_launch(void* const* d_in, const int* in_sizes, int n_in,
                              void* d_out, int out_size)
{
    const float* x   = (const float*)d_in[0];
    const int*   ei  = (const int*)d_in[1];
    const float* Wl  = (const float*)d_in[2];
    const float* bl  = (const float*)d_in[3];
    const float* Wr  = (const float*)d_in[4];
    const float* br  = (const float*)d_in[5];
    const float* att = (const float*)d_in[6];
    const float* cb  = (const float*)d_in[7];
    const float* W1  = (const float*)d_in[8];
    const float* b1  = (const float*)d_in[9];
    const float* W2  = (const float*)d_in[10];
    const float* b2  = (const float*)d_in[11];
    const float* Wc  = (const float*)d_in[12];
    const float* bc  = (const float*)d_in[13];

    const int n = in_sizes[0] / 512;
    const int E = in_sizes[1] / 2;
    const int total = E + n;
    const int* srcA = ei;
    const int* dstA = ei + E;

    float *xl, *xr;
    __half *xh, *hh, *Wlrt_h, *Wlrt_l, *W1t_h, *W1t_l;
    __nv_bfloat16 *h1h, *h1l, *h2h, *h2l, *W2t_h, *W2t_l, *Wct_h, *Wct_l;
    cudaGetSymbolAddress((void**)&xl,  g_xl);
    cudaGetSymbolAddress((void**)&xr,  g_xr);
    cudaGetSymbolAddress((void**)&xh,  g_xh);
    cudaGetSymbolAddress((void**)&hh,  g_hh);
    cudaGetSymbolAddress((void**)&h1h, g_h1h);
    cudaGetSymbolAddress((void**)&h1l, g_h1l);
    cudaGetSymbolAddress((void**)&h2h, g_h2h);
    cudaGetSymbolAddress((void**)&h2l, g_h2l);
    cudaGetSymbolAddress((void**)&Wlrt_h, g_Wlrt_h);
    cudaGetSymbolAddress((void**)&Wlrt_l, g_Wlrt_l);
    cudaGetSymbolAddress((void**)&W1t_h, g_W1t_h);
    cudaGetSymbolAddress((void**)&W1t_l, g_W1t_l);
    cudaGetSymbolAddress((void**)&W2t_h, g_W2t_h);
    cudaGetSymbolAddress((void**)&W2t_l, g_W2t_l);
    cudaGetSymbolAddress((void**)&Wct_h, g_Wct_h);
    cudaGetSymbolAddress((void**)&Wct_l, g_Wct_l);
    float* out = (float*)d_out;

    cudaFuncSetAttribute(gemm_mma_h<false, true, false, true>,
                         cudaFuncAttributeMaxDynamicSharedMemorySize, GSMEM_H);
    cudaFuncSetAttribute(gemm_mma_h<true, false, true, false>,
                         cudaFuncAttributeMaxDynamicSharedMemorySize, GSMEM_H);
    cudaFuncSetAttribute(gemm_mma<true, false, true>,
                         cudaFuncAttributeMaxDynamicSharedMemorySize, GSMEM);
    cudaFuncSetAttribute(gemm_mma<false, true, false>,
                         cudaFuncAttributeMaxDynamicSharedMemorySize, GSMEM);

    // side stream + events (created fresh per call; kernel_launch is invoked
    // only for the correctness run and the capture run, so no resource growth)
    cudaStream_t s2;
    cudaEvent_t evFork, evJoin;
    cudaStreamCreateWithFlags(&s2, cudaStreamNonBlocking);
    cudaEventCreateWithFlags(&evFork, cudaEventDisableTiming);
    cudaEventCreateWithFlags(&evJoin, cudaEventDisableTiming);

    // prep: split_x + weight splits + edge counting (deg zero-based)
    int nSplit = (n * 128 + 255) / 256;
    int nCount = (E + 255) / 256;
    prep_kernel<<<nSplit + 1616 + nCount, 256>>>(
        x, dstA, Wl, Wr, W1, W2, Wc,
        Wlrt_h, Wlrt_l, W1t_h, W1t_l, W2t_h, W2t_l, Wct_h, Wct_l,
        xh, n, E, nSplit);

    // fork: CSR chain (scan -> fill) on s2, concurrent with the xl|xr GEMM
    cudaEventRecord(evFork, 0);
    cudaStreamWaitEvent(s2, evFork, 0);
    scan_kernel<<<1, 1024, 0, s2>>>(n);
    fill_kernel<<<(total + 255) / 256, 256, 0, s2>>>(srcA, dstA, E, total);
    cudaEventRecord(evJoin, s2);

    // main: combined xl|xr transform (fp16 2-term, dual fp32 outputs)
    dim3 gx(2048 / 128, (n + 127) / 128);
    gemm_mma_h<false, true, false, true><<<gx, 256, GSMEM_H>>>(
        xh, Wlrt_h, Wlrt_l, bl, br, xl, xr, nullptr, nullptr, n, 2048, 512);

    // join before edge scoring (needs both CSR arrays and xl/xr)
    cudaStreamWaitEvent(0, evJoin, 0);

    edge_e_kernel<<<(total + 7) / 8, 256>>>(att, total);
    aggregate_kernel<<<n, 256>>>(cb);

    // MLP head: W1 fp16 2-term; W2/Wc bf16 3-term
    dim3 g1(512 / 128, (n + 127) / 128);
    gemm_mma_h<true, false, true, false><<<g1, 256, GSMEM_H>>>(
        hh, W1t_h, W1t_l, b1, nullptr, nullptr, nullptr, h1h, h1l, n, 512, 1024);
    dim3 g2(1, (n + 127) / 128);
    gemm_mma<true, false, true><<<g2, 256, GSMEM>>>(
        h1h, h1l, W2t_h, W2t_l, b2, nullptr, h2h, h2l, n, 128, 512);
    dim3 g3(1, (n + 127) / 128);
    gemm_mma<false, true, false><<<g3, 256, GSMEM>>>(
        h2h, h2l, Wct_h, Wct_l, bc, out, nullptr, nullptr, n, 100, 128);
}

// round 17
// speedup vs baseline: 1.1335x; 1.0945x over previous
#include <cuda_runtime.h>
#include <cuda_bf16.h>
#include <cuda_fp16.h>
#include <cstdint>

#define HID 1024
#define NEG_SLOPE 0.2f

static const int NMAX = 10240;
static const int EMAX = 163840;
#define TMAX (EMAX + NMAX)

// ---------------- scratch (static device globals) ----------------
__device__ __align__(16) float g_xl[(size_t)NMAX * HID];
__device__ __align__(16) float g_xr[(size_t)NMAX * HID];
__device__ __align__(16) float g_e [TMAX];
__device__ int   g_deg[NMAX];          // zero at start of every call (self-cleaning)
__device__ int   g_cur[NMAX];          // zeroed by scan before fill uses it
__device__ int   g_off[NMAX + 1];
__device__ int   g_srcs[TMAX];
__device__ int   g_dsts[TMAX];

// fp16 activations (2-term GEMM path)
__device__ __align__(16) __half g_xh[(size_t)NMAX * 512];
__device__ __align__(16) __half g_hh[(size_t)NMAX * HID];
// bf16 hi/lo activations (3-term path for W2/Wc)
__device__ __align__(16) __nv_bfloat16 g_h1h[(size_t)NMAX * 512];
__device__ __align__(16) __nv_bfloat16 g_h1l[(size_t)NMAX * 512];
__device__ __align__(16) __nv_bfloat16 g_h2h[(size_t)NMAX * 128];
__device__ __align__(16) __nv_bfloat16 g_h2l[(size_t)NMAX * 128];

// transposed + split weights: Wt[n][k]
__device__ __align__(16) __half g_Wlrt_h[2048 * 512], g_Wlrt_l[2048 * 512];
__device__ __align__(16) __half g_W1t_h[512 * 1024],  g_W1t_l[512 * 1024];
__device__ __align__(16) __nv_bfloat16 g_W2t_h[128 * 512], g_W2t_l[128 * 512];
__device__ __align__(16) __nv_bfloat16 g_Wct_h[112 * 128], g_Wct_l[112 * 128];

// ---------------- PTX helpers ----------------
__device__ __forceinline__ uint32_t smem_u32(const void* p) {
    uint32_t a;
    asm("{ .reg .u64 t; cvta.to.shared.u64 t, %1; cvt.u32.u64 %0, t; }"
        : "=r"(a) : "l"(p));
    return a;
}
__device__ __forceinline__ void cp16(uint32_t saddr, const void* gaddr, int srcsize) {
    asm volatile("cp.async.cg.shared.global [%0], [%1], 16, %2;"
                 :: "r"(saddr), "l"(gaddr), "r"(srcsize) : "memory");
}
#define CP_COMMIT() asm volatile("cp.async.commit_group;" ::: "memory")
#define CP_WAIT(n)  asm volatile("cp.async.wait_group %0;" :: "n"(n) : "memory")

__device__ __forceinline__ void ldsm4(uint32_t& r0, uint32_t& r1, uint32_t& r2,
                                      uint32_t& r3, uint32_t a) {
    asm volatile("ldmatrix.sync.aligned.m8n8.x4.shared.b16 {%0,%1,%2,%3}, [%4];"
                 : "=r"(r0), "=r"(r1), "=r"(r2), "=r"(r3) : "r"(a));
}
__device__ __forceinline__ void mma_bf16(float* d, const uint32_t* a,
                                         uint32_t b0, uint32_t b1) {
    asm volatile(
        "mma.sync.aligned.m16n8k16.row.col.f32.bf16.bf16.f32 "
        "{%0,%1,%2,%3}, {%4,%5,%6,%7}, {%8,%9}, {%0,%1,%2,%3};"
        : "+f"(d[0]), "+f"(d[1]), "+f"(d[2]), "+f"(d[3])
        : "r"(a[0]), "r"(a[1]), "r"(a[2]), "r"(a[3]), "r"(b0), "r"(b1));
}
__device__ __forceinline__ void mma_f16(float* d, const uint32_t* a,
                                        uint32_t b0, uint32_t b1) {
    asm volatile(
        "mma.sync.aligned.m16n8k16.row.col.f32.f16.f16.f32 "
        "{%0,%1,%2,%3}, {%4,%5,%6,%7}, {%8,%9}, {%0,%1,%2,%3};"
        : "+f"(d[0]), "+f"(d[1]), "+f"(d[2]), "+f"(d[3])
        : "r"(a[0]), "r"(a[1]), "r"(a[2]), "r"(a[3]), "r"(b0), "r"(b1));
}

#define TILE_B   8192

__device__ __forceinline__ void fill_tile_async(
    uint32_t dst, const void* __restrict__ src2B,
    int rowbase, int limit, int K, int k0, int tid)
{
    int fr = tid >> 2;
    int fc = tid & 3;
#pragma unroll
    for (int it = 0; it < 2; it++) {
        int row = fr + it * 64;
        int grow = rowbase + row;
        uint32_t saddr = dst + row * 64 + ((fc ^ ((row >> 1) & 3)) * 16);
        const char* g = (const char*)src2B + ((size_t)grow * K + k0 + fc * 8) * 2;
        cp16(saddr, g, (grow < limit) ? 16 : 0);
    }
}

// ============================================================================
// bf16 3-term GEMM (used for W2, Wc) — 2 CTAs/SM
// ============================================================================
#define STAGE_B  (4 * TILE_B)
#define GSMEM    (2 * STAGE_B)

template <bool RELU, bool WF32, bool WBF16>
__global__ __launch_bounds__(256, 2)
void gemm_mma(const __nv_bfloat16* __restrict__ Ah, const __nv_bfloat16* __restrict__ Al,
              const __nv_bfloat16* __restrict__ Bh, const __nv_bfloat16* __restrict__ Bl,
              const float* __restrict__ bias,
              float* __restrict__ C,
              __nv_bfloat16* __restrict__ Ch, __nv_bfloat16* __restrict__ Cl,
              int M, int Nn, int K)
{
    extern __shared__ char smem[];
    const uint32_t sb = smem_u32(smem);
    const int tid = threadIdx.x;
    const int wid = tid >> 5;
    const int lane = tid & 31;
    const int row0 = blockIdx.y * 128;
    const int col0 = blockIdx.x * 128;
    const int wm0 = (wid & 3) * 32;
    const int wn0 = (wid >> 2) * 64;

    float acc[2][8][4];
#pragma unroll
    for (int i = 0; i < 2; i++)
#pragma unroll
        for (int j = 0; j < 8; j++)
#pragma unroll
            for (int k = 0; k < 4; k++) acc[i][j][k] = 0.f;

    uint32_t aoff[2][2], boff[4][2];
#pragma unroll
    for (int mt = 0; mt < 2; mt++) {
        int arow = wm0 + mt * 16 + (lane & 15);
        int hi = lane >> 4;
#pragma unroll
        for (int s = 0; s < 2; s++) {
            int chunk = s * 2 + hi;
            aoff[mt][s] = arow * 64 + ((chunk ^ ((arow >> 1) & 3)) * 16);
        }
    }
#pragma unroll
    for (int bt = 0; bt < 4; bt++) {
        int brow = wn0 + bt * 16 + (lane & 7) + ((lane >> 4) & 1) * 8;
        int hi = (lane >> 3) & 1;
#pragma unroll
        for (int s = 0; s < 2; s++) {
            int chunk = s * 2 + hi;
            boff[bt][s] = brow * 64 + ((chunk ^ ((brow >> 1) & 3)) * 16);
        }
    }

    const int nC = K / 32;
    {
        uint32_t st = sb;
        fill_tile_async(st + 0 * TILE_B, Ah, row0, M,  K, 0, tid);
        fill_tile_async(st + 1 * TILE_B, Al, row0, M,  K, 0, tid);
        fill_tile_async(st + 2 * TILE_B, Bh, col0, Nn, K, 0, tid);
        fill_tile_async(st + 3 * TILE_B, Bl, col0, Nn, K, 0, tid);
        CP_COMMIT();
    }

    for (int c = 0; c < nC; c++) {
        const uint32_t st = sb + (c & 1) * STAGE_B;
        if (c + 1 < nC) {
            uint32_t nx = sb + ((c + 1) & 1) * STAGE_B;
            int k0 = (c + 1) * 32;
            fill_tile_async(nx + 0 * TILE_B, Ah, row0, M,  K, k0, tid);
            fill_tile_async(nx + 1 * TILE_B, Al, row0, M,  K, k0, tid);
            fill_tile_async(nx + 2 * TILE_B, Bh, col0, Nn, K, k0, tid);
            fill_tile_async(nx + 3 * TILE_B, Bl, col0, Nn, K, k0, tid);
            CP_COMMIT();
            CP_WAIT(1);
        } else {
            CP_WAIT(0);
        }
        __syncthreads();

#pragma unroll
        for (int s = 0; s < 2; s++) {
            uint32_t ah[2][4], al[2][4], bh[4][4], bl[4][4];
#pragma unroll
            for (int mt = 0; mt < 2; mt++) {
                ldsm4(ah[mt][0], ah[mt][1], ah[mt][2], ah[mt][3],
                      st + 0 * TILE_B + aoff[mt][s]);
                ldsm4(al[mt][0], al[mt][1], al[mt][2], al[mt][3],
                      st + 1 * TILE_B + aoff[mt][s]);
            }
#pragma unroll
            for (int bt = 0; bt < 4; bt++) {
                ldsm4(bh[bt][0], bh[bt][1], bh[bt][2], bh[bt][3],
                      st + 2 * TILE_B + boff[bt][s]);
                ldsm4(bl[bt][0], bl[bt][1], bl[bt][2], bl[bt][3],
                      st + 3 * TILE_B + boff[bt][s]);
            }
#pragma unroll
            for (int mt = 0; mt < 2; mt++) {
#pragma unroll
                for (int bt = 0; bt < 4; bt++) {
                    mma_bf16(acc[mt][2 * bt + 0], ah[mt], bh[bt][0], bh[bt][1]);
                    mma_bf16(acc[mt][2 * bt + 1], ah[mt], bh[bt][2], bh[bt][3]);
                    mma_bf16(acc[mt][2 * bt + 0], ah[mt], bl[bt][0], bl[bt][1]);
                    mma_bf16(acc[mt][2 * bt + 1], ah[mt], bl[bt][2], bl[bt][3]);
                    mma_bf16(acc[mt][2 * bt + 0], al[mt], bh[bt][0], bh[bt][1]);
                    mma_bf16(acc[mt][2 * bt + 1], al[mt], bh[bt][2], bh[bt][3]);
                }
            }
        }
        __syncthreads();
    }

#pragma unroll
    for (int mt = 0; mt < 2; mt++) {
#pragma unroll
        for (int nt = 0; nt < 8; nt++) {
            int col = col0 + wn0 + nt * 8 + (lane & 3) * 2;
            if (col >= Nn) continue;
            float bx = bias[col], by = bias[col + 1];
#pragma unroll
            for (int half = 0; half < 2; half++) {
                int grow = row0 + wm0 + mt * 16 + (lane >> 2) + half * 8;
                if (grow >= M) continue;
                float ox = acc[mt][nt][half * 2 + 0] + bx;
                float oy = acc[mt][nt][half * 2 + 1] + by;
                if (RELU) { ox = fmaxf(ox, 0.f); oy = fmaxf(oy, 0.f); }
                size_t idx = (size_t)grow * Nn + col;
                if (WF32) {
                    *(float2*)(C + idx) = make_float2(ox, oy);
                }
                if (WBF16) {
                    __nv_bfloat16 hx = __float2bfloat16(ox);
                    __nv_bfloat16 hy = __float2bfloat16(oy);
                    *(__nv_bfloat162*)(Ch + idx) = __nv_bfloat162(hx, hy);
                    *(__nv_bfloat162*)(Cl + idx) = __floats2bfloat162_rn(
                        ox - __bfloat162float(hx), oy - __bfloat162float(hy));
                }
            }
        }
    }
}

// ============================================================================
// fp16 2-term GEMM (A single fp16, B hi/lo) — 2 CTAs/SM
// ============================================================================
#define STAGE_H  (3 * TILE_B)
#define GSMEM_H  (2 * STAGE_H)

template <bool RELU, bool WF32, bool WBF16, bool SPLITC>
__global__ __launch_bounds__(256, 2)
void gemm_mma_h(const __half* __restrict__ Ah,
                const __half* __restrict__ Bh, const __half* __restrict__ Bl,
                const float* __restrict__ bias, const float* __restrict__ bias2,
                float* __restrict__ C, float* __restrict__ C2,
                __nv_bfloat16* __restrict__ Chb, __nv_bfloat16* __restrict__ Clb,
                int M, int Nn, int K)
{
    extern __shared__ char smem[];
    const uint32_t sb = smem_u32(smem);
    const int tid = threadIdx.x;
    const int wid = tid >> 5;
    const int lane = tid & 31;
    const int row0 = blockIdx.y * 128;
    const int col0 = blockIdx.x * 128;
    const int wm0 = (wid & 3) * 32;
    const int wn0 = (wid >> 2) * 64;

    float acc[2][8][4];
#pragma unroll
    for (int i = 0; i < 2; i++)
#pragma unroll
        for (int j = 0; j < 8; j++)
#pragma unroll
            for (int k = 0; k < 4; k++) acc[i][j][k] = 0.f;

    uint32_t aoff[2][2], boff[4][2];
#pragma unroll
    for (int mt = 0; mt < 2; mt++) {
        int arow = wm0 + mt * 16 + (lane & 15);
        int hi = lane >> 4;
#pragma unroll
        for (int s = 0; s < 2; s++) {
            int chunk = s * 2 + hi;
            aoff[mt][s] = arow * 64 + ((chunk ^ ((arow >> 1) & 3)) * 16);
        }
    }
#pragma unroll
    for (int bt = 0; bt < 4; bt++) {
        int brow = wn0 + bt * 16 + (lane & 7) + ((lane >> 4) & 1) * 8;
        int hi = (lane >> 3) & 1;
#pragma unroll
        for (int s = 0; s < 2; s++) {
            int chunk = s * 2 + hi;
            boff[bt][s] = brow * 64 + ((chunk ^ ((brow >> 1) & 3)) * 16);
        }
    }

    const int nC = K / 32;
    {
        uint32_t st = sb;
        fill_tile_async(st + 0 * TILE_B, Ah, row0, M,  K, 0, tid);
        fill_tile_async(st + 1 * TILE_B, Bh, col0, Nn, K, 0, tid);
        fill_tile_async(st + 2 * TILE_B, Bl, col0, Nn, K, 0, tid);
        CP_COMMIT();
    }

    for (int c = 0; c < nC; c++) {
        const uint32_t st = sb + (c & 1) * STAGE_H;
        if (c + 1 < nC) {
            uint32_t nx = sb + ((c + 1) & 1) * STAGE_H;
            int k0 = (c + 1) * 32;
            fill_tile_async(nx + 0 * TILE_B, Ah, row0, M,  K, k0, tid);
            fill_tile_async(nx + 1 * TILE_B, Bh, col0, Nn, K, k0, tid);
            fill_tile_async(nx + 2 * TILE_B, Bl, col0, Nn, K, k0, tid);
            CP_COMMIT();
            CP_WAIT(1);
        } else {
            CP_WAIT(0);
        }
        __syncthreads();

#pragma unroll
        for (int s = 0; s < 2; s++) {
            uint32_t ah[2][4], bh[4][4], bl[4][4];
#pragma unroll
            for (int mt = 0; mt < 2; mt++) {
                ldsm4(ah[mt][0], ah[mt][1], ah[mt][2], ah[mt][3],
                      st + 0 * TILE_B + aoff[mt][s]);
            }
#pragma unroll
            for (int bt = 0; bt < 4; bt++) {
                ldsm4(bh[bt][0], bh[bt][1], bh[bt][2], bh[bt][3],
                      st + 1 * TILE_B + boff[bt][s]);
                ldsm4(bl[bt][0], bl[bt][1], bl[bt][2], bl[bt][3],
                      st + 2 * TILE_B + boff[bt][s]);
            }
#pragma unroll
            for (int mt = 0; mt < 2; mt++) {
#pragma unroll
                for (int bt = 0; bt < 4; bt++) {
                    mma_f16(acc[mt][2 * bt + 0], ah[mt], bh[bt][0], bh[bt][1]);
                    mma_f16(acc[mt][2 * bt + 1], ah[mt], bh[bt][2], bh[bt][3]);
                    mma_f16(acc[mt][2 * bt + 0], ah[mt], bl[bt][0], bl[bt][1]);
                    mma_f16(acc[mt][2 * bt + 1], ah[mt], bl[bt][2], bl[bt][3]);
                }
            }
        }
        __syncthreads();
    }

#pragma unroll
    for (int mt = 0; mt < 2; mt++) {
#pragma unroll
        for (int nt = 0; nt < 8; nt++) {
            int col = col0 + wn0 + nt * 8 + (lane & 3) * 2;
            if (col >= Nn) continue;
            const float* bp = bias;
            float* Cp = C;
            int ccol = col;
            int cw = Nn;
            if (SPLITC) {
                cw = 1024;
                if (col >= 1024) { bp = bias2; Cp = C2; ccol = col - 1024; }
            }
            float bx = bp[ccol], by = bp[ccol + 1];
#pragma unroll
            for (int half = 0; half < 2; half++) {
                int grow = row0 + wm0 + mt * 16 + (lane >> 2) + half * 8;
                if (grow >= M) continue;
                float ox = acc[mt][nt][half * 2 + 0] + bx;
                float oy = acc[mt][nt][half * 2 + 1] + by;
                if (RELU) { ox = fmaxf(ox, 0.f); oy = fmaxf(oy, 0.f); }
                if (WF32) {
                    *(float2*)(Cp + (size_t)grow * cw + ccol) = make_float2(ox, oy);
                }
                if (WBF16) {
                    size_t idx = (size_t)grow * Nn + col;
                    __nv_bfloat16 hx = __float2bfloat16(ox);
                    __nv_bfloat16 hy = __float2bfloat16(oy);
                    *(__nv_bfloat162*)(Chb + idx) = __nv_bfloat162(hx, hy);
                    *(__nv_bfloat162*)(Clb + idx) = __floats2bfloat162_rn(
                        ox - __bfloat162float(hx), oy - __bfloat162float(hy));
                }
            }
        }
    }
}

// ============================================================================
// Prep (single launch: split_x + all weight splits + edge count)
// ============================================================================
__device__ __forceinline__ void tsplit_block_bf(
    const float* __restrict__ W, __nv_bfloat16* __restrict__ th,
    __nv_bfloat16* __restrict__ tl, int K, int N, int bx, int by, int tid)
{
    __shared__ float t[32][33];
    int k0 = by * 32, n0 = bx * 32;
    int tx = tid & 31, ty = tid >> 5;
#pragma unroll
    for (int i = 0; i < 4; i++) {
        int k = k0 + ty + i * 8;
        t[ty + i * 8][tx] = (k < K && n0 + tx < N) ? W[(size_t)k * N + n0 + tx] : 0.f;
    }
    __syncthreads();
#pragma unroll
    for (int i = 0; i < 4; i++) {
        int n = n0 + ty + i * 8;
        int k = k0 + tx;
        if (n < N && k < K) {
            float v = t[tx][ty + i * 8];
            __nv_bfloat16 hb = __float2bfloat16(v);
            th[(size_t)n * K + k] = hb;
            tl[(size_t)n * K + k] = __float2bfloat16(v - __bfloat162float(hb));
        }
    }
}
__device__ __forceinline__ void tsplit_block_h(
    const float* __restrict__ W, __half* __restrict__ th,
    __half* __restrict__ tl, int K, int N, int bx, int by, int tid)
{
    __shared__ float t[32][33];
    int k0 = by * 32, n0 = bx * 32;
    int tx = tid & 31, ty = tid >> 5;
#pragma unroll
    for (int i = 0; i < 4; i++) {
        int k = k0 + ty + i * 8;
        t[ty + i * 8][tx] = (k < K && n0 + tx < N) ? W[(size_t)k * N + n0 + tx] : 0.f;
    }
    __syncthreads();
#pragma unroll
    for (int i = 0; i < 4; i++) {
        int n = n0 + ty + i * 8;
        int k = k0 + tx;
        if (n < N && k < K) {
            float v = t[tx][ty + i * 8];
            __half hb = __float2half_rn(v);
            th[(size_t)n * K + k] = hb;
            tl[(size_t)n * K + k] = __float2half_rn(v - __half2float(hb));
        }
    }
}

__global__ __launch_bounds__(256)
void prep_kernel(const float* __restrict__ x, const int* __restrict__ dstA,
                 const float* __restrict__ Wl, const float* __restrict__ Wr,
                 const float* __restrict__ W1, const float* __restrict__ W2,
                 const float* __restrict__ Wc,
                 __half* Wlrt_h, __half* Wlrt_l,
                 __half* W1t_h, __half* W1t_l,
                 __nv_bfloat16* W2t_h, __nv_bfloat16* W2t_l,
                 __nv_bfloat16* Wct_h, __nv_bfloat16* Wct_l,
                 __half* xh,
                 int n, int E, int nSplit)
{
    int b = blockIdx.x;
    int tid = threadIdx.x;
    if (b < nSplit) {                                 // x -> fp16
        int i = b * 256 + tid;
        int n4 = n * 128;
        if (i < n4) {
            float4 v = ((const float4*)x)[i];
            __half2* h2 = (__half2*)xh;
            h2[i * 2 + 0] = __floats2half2_rn(v.x, v.y);
            h2[i * 2 + 1] = __floats2half2_rn(v.z, v.w);
        }
    } else if (b < nSplit + 512) {
        int bb = b - nSplit;
        tsplit_block_h(Wl, Wlrt_h, Wlrt_l, 512, 1024, bb & 31, bb >> 5, tid);
    } else if (b < nSplit + 1024) {
        int bb = b - nSplit - 512;
        tsplit_block_h(Wr, Wlrt_h + 1024 * 512, Wlrt_l + 1024 * 512,
                       512, 1024, bb & 31, bb >> 5, tid);
    } else if (b < nSplit + 1536) {
        int bb = b - nSplit - 1024;
        tsplit_block_h(W1, W1t_h, W1t_l, 1024, 512, bb & 15, bb >> 4, tid);
    } else if (b < nSplit + 1600) {
        int bb = b - nSplit - 1536;
        tsplit_block_bf(W2, W2t_h, W2t_l, 512, 128, bb & 3, bb >> 2, tid);
    } else if (b < nSplit + 1616) {
        int bb = b - nSplit - 1600;
        tsplit_block_bf(Wc, Wct_h, Wct_l, 128, 100, bb & 3, bb >> 2, tid);
    } else {                                          // edge count (deg zero-based)
        int k = (b - nSplit - 1616) * 256 + tid;
        if (k < E) atomicAdd(&g_deg[dstA[k]], 1);
    }
}

// ============================================================================
// CSR scan (shuffle-based) — adds +1 self-loop per node; zeroes deg/cur.
// ============================================================================
__global__ __launch_bounds__(1024)
void scan_kernel(int n) {
    __shared__ int warpsum[32];
    int tid = threadIdx.x;
    int lane = tid & 31, wrp = tid >> 5;
    int chunk = (n + 1023) >> 10;
    int beg = min(tid * chunk, n);
    int end = min(beg + chunk, n);
    int s = 0;
    for (int i = beg; i < end; i++) s += g_deg[i] + 1;
    int v = s;
#pragma unroll
    for (int o = 1; o < 32; o <<= 1) {
        int t = __shfl_up_sync(0xffffffffu, v, o);
        if (lane >= o) v += t;
    }
    if (lane == 31) warpsum[wrp] = v;
    __syncthreads();
    if (wrp == 0) {
        int w = warpsum[lane];
#pragma unroll
        for (int o = 1; o < 32; o <<= 1) {
            int t = __shfl_up_sync(0xffffffffu, w, o);
            if (lane >= o) w += t;
        }
        warpsum[lane] = w;
    }
    __syncthreads();
    int run = v - s + ((wrp > 0) ? warpsum[wrp - 1] : 0);
    for (int i = beg; i < end; i++) {
        g_off[i] = run;
        run += g_deg[i] + 1;
        g_deg[i] = 0;
        g_cur[i] = 0;
    }
    if (tid == 1023) g_off[n] = warpsum[31];
}

__global__ void fill_kernel(const int* __restrict__ src, const int* __restrict__ dst,
                            int E, int total) {
    int k = blockIdx.x * blockDim.x + threadIdx.x;
    if (k >= total) return;
    int d = (k < E) ? dst[k] : (k - E);
    int s = (k < E) ? src[k] : (k - E);
    int pos = atomicAdd(&g_cur[d], 1);
    int p = g_off[d] + pos;
    g_srcs[p] = s;
    g_dsts[p] = d;
}

// ============================================================================
// Edge scores over dst-sorted positions
// ============================================================================
__global__ __launch_bounds__(256)
void edge_e_kernel(const float* __restrict__ att, int total)
{
    int w = blockIdx.x * 8 + (threadIdx.x >> 5);
    if (w >= total) return;
    int lane = threadIdx.x & 31;
    int s = g_srcs[w];
    int d = g_dsts[w];
    const float4* xl4 = (const float4*)(g_xl + (size_t)s * HID);
    const float4* xr4 = (const float4*)(g_xr + (size_t)d * HID);
    const float4* at4 = (const float4*)att;
    float acc = 0.f;
#pragma unroll
    for (int j = 0; j < 8; j++) {
        int idx = lane + j * 32;
        float4 a = xl4[idx];
        float4 b = xr4[idx];
        float4 t = at4[idx];
        float v;
        v = a.x + b.x; v = (v > 0.f) ? v : NEG_SLOPE * v; acc = fmaf(v, t.x, acc);
        v = a.y + b.y; v = (v > 0.f) ? v : NEG_SLOPE * v; acc = fmaf(v, t.y, acc);
        v = a.z + b.z; v = (v > 0.f) ? v : NEG_SLOPE * v; acc = fmaf(v, t.z, acc);
        v = a.w + b.w; v = (v > 0.f) ? v : NEG_SLOPE * v; acc = fmaf(v, t.w, acc);
    }
#pragma unroll
    for (int o = 16; o > 0; o >>= 1) acc += __shfl_xor_sync(0xffffffffu, acc, o);
    if (lane == 0) g_e[w] = acc;
}

// ============================================================================
// Segment softmax + aggregation (fp32; writes fp16 h)
// ============================================================================
#define DEGCAP 1024
__global__ __launch_bounds__(256)
void aggregate_kernel(const float* __restrict__ conv_b)
{
    int node = blockIdx.x;
    int tid = threadIdx.x;
    int beg = g_off[node];
    int deg = g_off[node + 1] - beg;

    __shared__ float s_w[DEGCAP];
    __shared__ int   s_src[DEGCAP];
    __shared__ float red[256];

    float m, ssum;
    float4 acc = make_float4(0.f, 0.f, 0.f, 0.f);

    if (deg <= DEGCAP) {
        for (int j = tid; j < deg; j += 256) {
            s_w[j] = g_e[beg + j];
            s_src[j] = g_srcs[beg + j];
        }
        __syncthreads();
        float mx = -1e30f;
        for (int j = tid; j < deg; j += 256) mx = fmaxf(mx, s_w[j]);
        red[tid] = mx; __syncthreads();
        for (int o = 128; o > 0; o >>= 1) {
            if (tid < o) red[tid] = fmaxf(red[tid], red[tid + o]);
            __syncthreads();
        }
        m = red[0];
        __syncthreads();
        for (int j = tid; j < deg; j += 256) s_w[j] = __expf(s_w[j] - m);
        float sl = 0.f;
        for (int j = tid; j < deg; j += 256) sl += s_w[j];
        red[tid] = sl; __syncthreads();
        for (int o = 128; o > 0; o >>= 1) {
            if (tid < o) red[tid] += red[tid + o];
            __syncthreads();
        }
        ssum = red[0];
        __syncthreads();
        int j = 0;
        for (; j + 3 < deg; j += 4) {
            float w0 = s_w[j + 0], w1 = s_w[j + 1], w2 = s_w[j + 2], w3 = s_w[j + 3];
            const float4* r0 = (const float4*)(g_xl + (size_t)s_src[j + 0] * HID);
            const float4* r1 = (const float4*)(g_xl + (size_t)s_src[j + 1] * HID);
            const float4* r2 = (const float4*)(g_xl + (size_t)s_src[j + 2] * HID);
            const float4* r3 = (const float4*)(g_xl + (size_t)s_src[j + 3] * HID);
            float4 v0 = r0[tid], v1 = r1[tid], v2 = r2[tid], v3 = r3[tid];
            acc.x = fmaf(w0, v0.x, acc.x); acc.y = fmaf(w0, v0.y, acc.y);
            acc.z = fmaf(w0, v0.z, acc.z); acc.w = fmaf(w0, v0.w, acc.w);
            acc.x = fmaf(w1, v1.x, acc.x); acc.y = fmaf(w1, v1.y, acc.y);
            acc.z = fmaf(w1, v1.z, acc.z); acc.w = fmaf(w1, v1.w, acc.w);
            acc.x = fmaf(w2, v2.x, acc.x); acc.y = fmaf(w2, v2.y, acc.y);
            acc.z = fmaf(w2, v2.z, acc.z); acc.w = fmaf(w2, v2.w, acc.w);
            acc.x = fmaf(w3, v3.x, acc.x); acc.y = fmaf(w3, v3.y, acc.y);
            acc.z = fmaf(w3, v3.z, acc.z); acc.w = fmaf(w3, v3.w, acc.w);
        }
        for (; j < deg; j++) {
            float wgt = s_w[j];
            const float4* row = (const float4*)(g_xl + (size_t)s_src[j] * HID);
            float4 v = row[tid];
            acc.x = fmaf(wgt, v.x, acc.x);
            acc.y = fmaf(wgt, v.y, acc.y);
            acc.z = fmaf(wgt, v.z, acc.z);
            acc.w = fmaf(wgt, v.w, acc.w);
        }
    } else {
        float mx = -1e30f;
        for (int j = tid; j < deg; j += 256) mx = fmaxf(mx, g_e[beg + j]);
        red[tid] = mx; __syncthreads();
        for (int o = 128; o > 0; o >>= 1) {
            if (tid < o) red[tid] = fmaxf(red[tid], red[tid + o]);
            __syncthreads();
        }
        m = red[0];
        __syncthreads();
        float sl = 0.f;
        for (int j = tid; j < deg; j += 256) sl += __expf(g_e[beg + j] - m);
        red[tid] = sl; __syncthreads();
        for (int o = 128; o > 0; o >>= 1) {
            if (tid < o) red[tid] += red[tid + o];
            __syncthreads();
        }
        ssum = red[0];
        __syncthreads();
        for (int j = 0; j < deg; j++) {
            float wgt = __expf(g_e[beg + j] - m);
            const float4* row = (const float4*)(g_xl + (size_t)g_srcs[beg + j] * HID);
            float4 v = row[tid];
            acc.x = fmaf(wgt, v.x, acc.x);
            acc.y = fmaf(wgt, v.y, acc.y);
            acc.z = fmaf(wgt, v.z, acc.z);
            acc.w = fmaf(wgt, v.w, acc.w);
        }
    }

    float inv = 1.f / ssum;
    float4 cb = ((const float4*)conv_b)[tid];
    float ox = fmaxf(fmaf(acc.x, inv, cb.x), 0.f);
    float oy = fmaxf(fmaf(acc.y, inv, cb.y), 0.f);
    float oz = fmaxf(fmaf(acc.z, inv, cb.z), 0.f);
    float ow = fmaxf(fmaf(acc.w, inv, cb.w), 0.f);
    __half2* hp = (__half2*)(g_hh + (size_t)node * HID + tid * 4);
    hp[0] = __floats2half2_rn(ox, oy);
    hp[1] = __floats2half2_rn(oz, ow);
}

// ============================================================================
// launch — capture-safe stream fork/join (CSR chain under xl|xr GEMM)
// ============================================================================
extern "C" void kernel_launch(void* const* d_in, const int* in_sizes, int n_in,
                              void* d_out, int out_size)
{
    const float* x   = (const float*)d_in[0];
    const int*   ei  = (const int*)d_in[1];
    const float* Wl  = (const float*)d_in[2];
    const float* bl  = (const float*)d_in[3];
    const float* Wr  = (const float*)d_in[4];
    const float* br  = (const float*)d_in[5];
    const float* att = (const float*)d_in[6];
    const float* cb  = (const float*)d_in[7];
    const float* W1  = (const float*)d_in[8];
    const float* b1  = (const float*)d_in[9];
    const float* W2  = (const float*)d_in[10];
    const float* b2  = (const float*)d_in[11];
    const float* Wc  = (const float*)d_in[12];
    const float* bc  = (const float*)d_in[13];

    const int n = in_sizes[0] / 512;
    const int E = in_sizes[1] / 2;
    const int total = E + n;
    const int* srcA = ei;
    const int* dstA = ei + E;

    float *xl, *xr;
    __half *xh, *hh, *Wlrt_h, *Wlrt_l, *W1t_h, *W1t_l;
    __nv_bfloat16 *h1h, *h1l, *h2h, *h2l, *W2t_h, *W2t_l, *Wct_h, *Wct_l;
    cudaGetSymbolAddress((void**)&xl,  g_xl);
    cudaGetSymbolAddress((void**)&xr,  g_xr);
    cudaGetSymbolAddress((void**)&xh,  g_xh);
    cudaGetSymbolAddress((void**)&hh,  g_hh);
    cudaGetSymbolAddress((void**)&h1h, g_h1h);
    cudaGetSymbolAddress((void**)&h1l, g_h1l);
    cudaGetSymbolAddress((void**)&h2h, g_h2h);
    cudaGetSymbolAddress((void**)&h2l, g_h2l);
    cudaGetSymbolAddress((void**)&Wlrt_h, g_Wlrt_h);
    cudaGetSymbolAddress((void**)&Wlrt_l, g_Wlrt_l);
    cudaGetSymbolAddress((void**)&W1t_h, g_W1t_h);
    cudaGetSymbolAddress((void**)&W1t_l, g_W1t_l);
    cudaGetSymbolAddress((void**)&W2t_h, g_W2t_h);
    cudaGetSymbolAddress((void**)&W2t_l, g_W2t_l);
    cudaGetSymbolAddress((void**)&Wct_h, g_Wct_h);
    cudaGetSymbolAddress((void**)&Wct_l, g_Wct_l);
    float* out = (float*)d_out;

    cudaFuncSetAttribute(gemm_mma_h<false, true, false, true>,
                         cudaFuncAttributeMaxDynamicSharedMemorySize, GSMEM_H);
    cudaFuncSetAttribute(gemm_mma_h<true, false, true, false>,
                         cudaFuncAttributeMaxDynamicSharedMemorySize, GSMEM_H);
    cudaFuncSetAttribute(gemm_mma<true, false, true>,
                         cudaFuncAttributeMaxDynamicSharedMemorySize, GSMEM);
    cudaFuncSetAttribute(gemm_mma<false, true, false>,
                         cudaFuncAttributeMaxDynamicSharedMemorySize, GSMEM);

    cudaStream_t s2;
    cudaEvent_t evFork, evJoin;
    cudaStreamCreateWithFlags(&s2, cudaStreamNonBlocking);
    cudaEventCreateWithFlags(&evFork, cudaEventDisableTiming);
    cudaEventCreateWithFlags(&evJoin, cudaEventDisableTiming);

    // prep: split_x + weight splits + edge counting (deg zero-based)
    int nSplit = (n * 128 + 255) / 256;
    int nCount = (E + 255) / 256;
    prep_kernel<<<nSplit + 1616 + nCount, 256>>>(
        x, dstA, Wl, Wr, W1, W2, Wc,
        Wlrt_h, Wlrt_l, W1t_h, W1t_l, W2t_h, W2t_l, Wct_h, Wct_l,
        xh, n, E, nSplit);

    // fork: CSR chain (scan -> fill) on s2, concurrent with the xl|xr GEMM
    cudaEventRecord(evFork, 0);
    cudaStreamWaitEvent(s2, evFork, 0);
    scan_kernel<<<1, 1024, 0, s2>>>(n);
    fill_kernel<<<(total + 255) / 256, 256, 0, s2>>>(srcA, dstA, E, total);
    cudaEventRecord(evJoin, s2);

    // main: combined xl|xr transform (fp16 2-term, dual fp32 outputs)
    dim3 gx(2048 / 128, (n + 127) / 128);
    gemm_mma_h<false, true, false, true><<<gx, 256, GSMEM_H>>>(
        xh, Wlrt_h, Wlrt_l, bl, br, xl, xr, nullptr, nullptr, n, 2048, 512);

    cudaStreamWaitEvent(0, evJoin, 0);

    edge_e_kernel<<<(total + 7) / 8, 256>>>(att, total);
    aggregate_kernel<<<n, 256>>>(cb);

    // MLP head: W1 fp16 2-term; W2/Wc bf16 3-term
    dim3 g1(512 / 128, (n + 127) / 128);
    gemm_mma_h<true, false, true, false><<<g1, 256, GSMEM_H>>>(
        hh, W1t_h, W1t_l, b1, nullptr, nullptr, nullptr, h1h, h1l, n, 512, 1024);
    dim3 g2(1, (n + 127) / 128);
    gemm_mma<true, false, true><<<g2, 256, GSMEM>>>(
        h1h, h1l, W2t_h, W2t_l, b2, nullptr, h2h, h2l, n, 128, 512);
    dim3 g3(1, (n + 127) / 128);
    gemm_mma<false, true, false><<<g3, 256, GSMEM>>>(
        h2h, h2l, Wct_h, Wct_l, bc, out, nullptr, nullptr, n, 100, 128);
}